// round 1
// baseline (speedup 1.0000x reference)
#include <cuda_runtime.h>

// FixedTopKLoRALinear — Round 1 baseline.
//   out = x @ W^T + bias + (soft_topk(x @ A^T) @ B^T) * SCALE
// Shapes (hardcoded, fixed problem): x[8192,4096], W[4096,4096], A[64,4096],
// B[4096,64], bias[4096]. SCALE = 16/16 = 1.0.
//
// Kernel 1: z = x A^T, per-row 16th-largest |z| threshold, sigmoid soft mask,
//           writes z_sparse to __device__ scratch.
// Kernel 2: fused SGEMM (128x128x16 tiles, fma.rn.f32x2 inner loop), LoRA term
//           appended as 4 extra K-tiles, bias added in epilogue.

typedef unsigned long long u64;

#define DIN   4096
#define DOUT  4096
#define MROWS 8192
#define RNK   64
#define KTOP  16
// TEMP = 0.1 -> multiply by 10.0f ; SCALE = 1.0f (folded, omitted)

__device__ float g_z[(size_t)MROWS * RNK];   // z_sparse scratch (2 MB)

__device__ __forceinline__ u64 pack2(float lo, float hi) {
    u64 r; asm("mov.b64 %0, {%1, %2};" : "=l"(r) : "f"(lo), "f"(hi)); return r;
}
__device__ __forceinline__ void unpack2(u64 v, float& lo, float& hi) {
    asm("mov.b64 {%0, %1}, %2;" : "=f"(lo), "=f"(hi) : "l"(v));
}
// packed dual-FMA: acc = a * b + acc  (2x fp32 per instruction on sm_103a)
__device__ __forceinline__ void fma2(u64& acc, u64 a, u64 b) {
    asm("fma.rn.f32x2 %0, %1, %2, %0;" : "+l"(acc) : "l"(a), "l"(b));
}

// ---------------------------------------------------------------------------
// Kernel 1: z = x @ A^T (64 rows x 64 ranks per block), topk mask, store z_sparse
// ---------------------------------------------------------------------------
__global__ __launch_bounds__(256) void lora_z_topk_kernel(
    const float* __restrict__ x, const float* __restrict__ A)
{
    __shared__ __align__(16) float As[16][64];
    __shared__ __align__(16) float Bs[16][64];
    __shared__ float zt[64][65];

    const int tid  = threadIdx.x;
    const int row0 = blockIdx.x * 64;
    const int tx   = (tid & 15) * 4;   // rank (output col) base, 0..60
    const int ty   = (tid >> 4) * 4;   // row base, 0..60
    const int lr   = tid >> 2;         // load row 0..63
    const int lc   = (tid & 3) * 4;    // load col 0,4,8,12

    const float* xp = x + (size_t)(row0 + lr) * DIN + lc;
    const float* Ap = A + (size_t)lr * DIN + lc;

    u64 acc[4][2];
    #pragma unroll
    for (int i = 0; i < 4; ++i) { acc[i][0] = 0ull; acc[i][1] = 0ull; }

    float4 ra = *(const float4*)xp;
    float4 rb = *(const float4*)Ap;

    for (int kt = 0; kt < DIN; kt += 16) {
        As[lc+0][lr] = ra.x; As[lc+1][lr] = ra.y; As[lc+2][lr] = ra.z; As[lc+3][lr] = ra.w;
        Bs[lc+0][lr] = rb.x; Bs[lc+1][lr] = rb.y; Bs[lc+2][lr] = rb.z; Bs[lc+3][lr] = rb.w;
        __syncthreads();
        if (kt + 16 < DIN) {
            ra = *(const float4*)(xp + kt + 16);
            rb = *(const float4*)(Ap + kt + 16);
        }
        #pragma unroll
        for (int k = 0; k < 16; ++k) {
            float4 av = *(const float4*)&As[k][ty];
            const u64* bq = (const u64*)&Bs[k][tx];
            u64 b0 = bq[0], b1 = bq[1];
            float a[4] = {av.x, av.y, av.z, av.w};
            #pragma unroll
            for (int i = 0; i < 4; ++i) {
                u64 a2 = pack2(a[i], a[i]);
                fma2(acc[i][0], a2, b0);
                fma2(acc[i][1], a2, b1);
            }
        }
        __syncthreads();
    }

    #pragma unroll
    for (int i = 0; i < 4; ++i) {
        float v0, v1, v2, v3;
        unpack2(acc[i][0], v0, v1);
        unpack2(acc[i][1], v2, v3);
        zt[ty+i][tx+0] = v0; zt[ty+i][tx+1] = v1;
        zt[ty+i][tx+2] = v2; zt[ty+i][tx+3] = v3;
    }
    __syncthreads();

    // Per-row soft top-k: threshold = 16th largest |z| (rank-count, tie-safe).
    if (tid < 64) {
        const int row = tid;
        float thr = 0.0f;
        for (int i = 0; i < RNK; ++i) {
            float vi = fabsf(zt[row][i]);
            int gt = 0, ge = 0;
            for (int j = 0; j < RNK; ++j) {
                float vj = fabsf(zt[row][j]);
                gt += (vj > vi);
                ge += (vj >= vi);
            }
            if (gt < KTOP && ge >= KTOP) thr = vi;
        }
        float* zo = g_z + (size_t)(row0 + row) * RNK;
        for (int r = 0; r < RNK; ++r) {
            float zv = zt[row][r];
            float m  = 1.0f / (1.0f + expf((thr - fabsf(zv)) * 10.0f));
            zo[r] = zv * m;   // SCALE == 1.0
        }
    }
}

// ---------------------------------------------------------------------------
// Kernel 2: out = x W^T + bias + z_sparse B^T   (128x128 tile, 8x8 per thread)
// ---------------------------------------------------------------------------
__device__ __forceinline__ void tile_fma(const float (&As)[16][128],
                                         const float (&Bs)[16][128],
                                         u64 (&acc)[8][4], int tx, int ty)
{
    #pragma unroll
    for (int k = 0; k < 16; ++k) {
        float4 a0 = *(const float4*)&As[k][ty];
        float4 a1 = *(const float4*)&As[k][ty + 64];
        const u64* blo = (const u64*)&Bs[k][tx];
        const u64* bhi = (const u64*)&Bs[k][tx + 64];
        u64 b[4] = {blo[0], blo[1], bhi[0], bhi[1]};
        float a[8] = {a0.x, a0.y, a0.z, a0.w, a1.x, a1.y, a1.z, a1.w};
        #pragma unroll
        for (int i = 0; i < 8; ++i) {
            u64 a2 = pack2(a[i], a[i]);
            #pragma unroll
            for (int j = 0; j < 4; ++j) fma2(acc[i][j], a2, b[j]);
        }
    }
}

__global__ __launch_bounds__(256, 2) void fused_gemm_kernel(
    const float* __restrict__ x, const float* __restrict__ W,
    const float* __restrict__ Bm, const float* __restrict__ bias,
    float* __restrict__ out)
{
    __shared__ __align__(16) float As[16][128];
    __shared__ __align__(16) float Bs[16][128];

    const int tid  = threadIdx.x;
    const int row0 = blockIdx.y * 128;
    const int col0 = blockIdx.x * 128;
    const int tx   = (tid & 15) * 4;   // out col base (and +64)
    const int ty   = (tid >> 4) * 4;   // out row base (and +64)
    const int lr   = tid >> 2;         // load row 0..63 (and +64)
    const int lc   = (tid & 3) * 4;    // load col 0,4,8,12

    const float* xp0 = x + (size_t)(row0 + lr) * DIN + lc;
    const float* xp1 = xp0 + (size_t)64 * DIN;
    const float* wp0 = W + (size_t)(col0 + lr) * DIN + lc;
    const float* wp1 = wp0 + (size_t)64 * DIN;

    u64 acc[8][4];
    #pragma unroll
    for (int i = 0; i < 8; ++i)
        #pragma unroll
        for (int j = 0; j < 4; ++j) acc[i][j] = 0ull;

    float4 ra0 = *(const float4*)xp0;
    float4 ra1 = *(const float4*)xp1;
    float4 rb0 = *(const float4*)wp0;
    float4 rb1 = *(const float4*)wp1;

    // Main K loop over D_IN (register-prefetch double buffering)
    for (int kt = 0; kt < DIN; kt += 16) {
        As[lc+0][lr]    = ra0.x; As[lc+1][lr]    = ra0.y; As[lc+2][lr]    = ra0.z; As[lc+3][lr]    = ra0.w;
        As[lc+0][lr+64] = ra1.x; As[lc+1][lr+64] = ra1.y; As[lc+2][lr+64] = ra1.z; As[lc+3][lr+64] = ra1.w;
        Bs[lc+0][lr]    = rb0.x; Bs[lc+1][lr]    = rb0.y; Bs[lc+2][lr]    = rb0.z; Bs[lc+3][lr]    = rb0.w;
        Bs[lc+0][lr+64] = rb1.x; Bs[lc+1][lr+64] = rb1.y; Bs[lc+2][lr+64] = rb1.z; Bs[lc+3][lr+64] = rb1.w;
        __syncthreads();
        if (kt + 16 < DIN) {
            ra0 = *(const float4*)(xp0 + kt + 16);
            ra1 = *(const float4*)(xp1 + kt + 16);
            rb0 = *(const float4*)(wp0 + kt + 16);
            rb1 = *(const float4*)(wp1 + kt + 16);
        }
        tile_fma(As, Bs, acc, tx, ty);
        __syncthreads();
    }

    // LoRA tail: 4 more K-tiles over rank dim (A-src = z_sparse, B-src = B)
    const float* zp0 = g_z + (size_t)(row0 + lr) * RNK + lc;
    const float* zp1 = zp0 + (size_t)64 * RNK;
    const float* bp0 = Bm + (size_t)(col0 + lr) * RNK + lc;
    const float* bp1 = bp0 + (size_t)64 * RNK;
    for (int kt = 0; kt < RNK; kt += 16) {
        float4 za0 = *(const float4*)(zp0 + kt);
        float4 za1 = *(const float4*)(zp1 + kt);
        float4 zb0 = *(const float4*)(bp0 + kt);
        float4 zb1 = *(const float4*)(bp1 + kt);
        As[lc+0][lr]    = za0.x; As[lc+1][lr]    = za0.y; As[lc+2][lr]    = za0.z; As[lc+3][lr]    = za0.w;
        As[lc+0][lr+64] = za1.x; As[lc+1][lr+64] = za1.y; As[lc+2][lr+64] = za1.z; As[lc+3][lr+64] = za1.w;
        Bs[lc+0][lr]    = zb0.x; Bs[lc+1][lr]    = zb0.y; Bs[lc+2][lr]    = zb0.z; Bs[lc+3][lr]    = zb0.w;
        Bs[lc+0][lr+64] = zb1.x; Bs[lc+1][lr+64] = zb1.y; Bs[lc+2][lr+64] = zb1.z; Bs[lc+3][lr+64] = zb1.w;
        __syncthreads();
        tile_fma(As, Bs, acc, tx, ty);
        __syncthreads();
    }

    // Epilogue: + bias, vectorized stores
    float4 bias_lo = *(const float4*)&bias[col0 + tx];
    float4 bias_hi = *(const float4*)&bias[col0 + tx + 64];
    #pragma unroll
    for (int i = 0; i < 8; ++i) {
        int m = row0 + ((i < 4) ? (ty + i) : (64 + ty + i - 4));
        float v0, v1, v2, v3, v4, v5, v6, v7;
        unpack2(acc[i][0], v0, v1);
        unpack2(acc[i][1], v2, v3);
        unpack2(acc[i][2], v4, v5);
        unpack2(acc[i][3], v6, v7);
        float4 o_lo = make_float4(v0 + bias_lo.x, v1 + bias_lo.y, v2 + bias_lo.z, v3 + bias_lo.w);
        float4 o_hi = make_float4(v4 + bias_hi.x, v5 + bias_hi.y, v6 + bias_hi.z, v7 + bias_hi.w);
        *(float4*)&out[(size_t)m * DOUT + col0 + tx]      = o_lo;
        *(float4*)&out[(size_t)m * DOUT + col0 + tx + 64] = o_hi;
    }
}

// ---------------------------------------------------------------------------
extern "C" void kernel_launch(void* const* d_in, const int* in_sizes, int n_in,
                              void* d_out, int out_size)
{
    const float* x    = (const float*)d_in[0];   // [8192, 4096]
    const float* A    = (const float*)d_in[1];   // [64, 4096]
    const float* Bm   = (const float*)d_in[2];   // [4096, 64]
    const float* W    = (const float*)d_in[3];   // [4096, 4096]
    const float* bias = (const float*)d_in[4];   // [4096]
    float* out = (float*)d_out;                  // [8192, 4096]

    lora_z_topk_kernel<<<MROWS / 64, 256>>>(x, A);

    dim3 grid(DOUT / 128, MROWS / 128);
    fused_gemm_kernel<<<grid, 256>>>(x, W, Bm, bias, out);
}

// round 3
// speedup vs baseline: 1.8970x; 1.8970x over previous
#include <cuda_runtime.h>
#include <cstdint>

// FixedTopKLoRALinear — Round 3: tf32 mma.sync (legacy tensor path, works on
// plain sm_103 target; tcgen05 needs sm_103a which this toolchain's ptxas
// stage rejects).
//   out = x @ W^T + bias + soft_topk(x @ A^T) @ B^T    (SCALE = 1.0)
// x[8192,4096] W[4096,4096] A[64,4096] B[4096,64] bias[4096], all fp32.

typedef unsigned long long u64;

#define DIN   4096
#define DOUT  4096
#define MROWS 8192
#define RNK   64
#define KTOP  16

// ---- kernel 2 tiling ----
#define BM 128
#define BN 128
#define BK 32
#define KCHUNKS (DIN / BK)                 // 128
#define NITER   (KCHUNKS + RNK / BK)       // 130

// padded smem layout: row = 8 tf32 (4 k-pairs) = 32B + 8B pad = 40B
#define ROWB    40
#define SLICEB  (128 * ROWB + 32)          // 5152 (pad keeps slices bank-shifted)
#define REGB    (4 * SLICEB)               // 20608 per matrix per stage
#define STAGEB  (2 * REGB)                 // 41216
#define SMEMB   (2 * STAGEB)               // 82432

__device__ float g_z[(size_t)MROWS * RNK];   // z_sparse scratch (2 MB)

// ---------------------------------------------------------------------------
// helpers
// ---------------------------------------------------------------------------
// round-to-nearest fp32 -> tf32 pair (bit trick: +0x1000 then HW truncates)
__device__ __forceinline__ float2 rnd2(uint32_t a, uint32_t b) {
    float2 r;
    r.x = __uint_as_float(a + 0x1000u);
    r.y = __uint_as_float(b + 0x1000u);
    return r;
}

// m16n8k8 tf32 mma. a02 = (a0,a2) row r, a13 = (a1,a3) row r+8, b01 = (b0,b1).
__device__ __forceinline__ void mma16818(float* d, float2 a02, float2 a13, float2 b01) {
    asm("mma.sync.aligned.m16n8k8.row.col.f32.tf32.tf32.f32 "
        "{%0,%1,%2,%3}, {%4,%5,%6,%7}, {%8,%9}, {%0,%1,%2,%3};"
        : "+f"(d[0]), "+f"(d[1]), "+f"(d[2]), "+f"(d[3])
        : "r"(__float_as_uint(a02.x)), "r"(__float_as_uint(a13.x)),
          "r"(__float_as_uint(a02.y)), "r"(__float_as_uint(a13.y)),
          "r"(__float_as_uint(b01.x)), "r"(__float_as_uint(b01.y)));
}

// ---------------------------------------------------------------------------
// Kernel 1: z = x @ A^T, exact 16th-largest-|z| threshold, sigmoid soft mask.
// GEMM part = validated round-1 code; top-k now warp-parallel (extract-max x16).
// ---------------------------------------------------------------------------
__device__ __forceinline__ u64 pack2(float lo, float hi) {
    u64 r; asm("mov.b64 %0, {%1, %2};" : "=l"(r) : "f"(lo), "f"(hi)); return r;
}
__device__ __forceinline__ void unpack2(u64 v, float& lo, float& hi) {
    asm("mov.b64 {%0, %1}, %2;" : "=f"(lo), "=f"(hi) : "l"(v));
}
__device__ __forceinline__ void fma2(u64& acc, u64 a, u64 b) {
    asm("fma.rn.f32x2 %0, %1, %2, %0;" : "+l"(acc) : "l"(a), "l"(b));
}

__global__ __launch_bounds__(256) void lora_z_topk_kernel(
    const float* __restrict__ x, const float* __restrict__ A)
{
    __shared__ __align__(16) float As[16][64];
    __shared__ __align__(16) float Bs[16][64];
    __shared__ float zt[64][65];

    const int tid  = threadIdx.x;
    const int row0 = blockIdx.x * 64;
    const int tx   = (tid & 15) * 4;
    const int ty   = (tid >> 4) * 4;
    const int lr   = tid >> 2;
    const int lc   = (tid & 3) * 4;

    const float* xp = x + (size_t)(row0 + lr) * DIN + lc;
    const float* Ap = A + (size_t)lr * DIN + lc;

    u64 acc[4][2];
    #pragma unroll
    for (int i = 0; i < 4; ++i) { acc[i][0] = 0ull; acc[i][1] = 0ull; }

    float4 ra = *(const float4*)xp;
    float4 rb = *(const float4*)Ap;

    for (int kt = 0; kt < DIN; kt += 16) {
        As[lc+0][lr] = ra.x; As[lc+1][lr] = ra.y; As[lc+2][lr] = ra.z; As[lc+3][lr] = ra.w;
        Bs[lc+0][lr] = rb.x; Bs[lc+1][lr] = rb.y; Bs[lc+2][lr] = rb.z; Bs[lc+3][lr] = rb.w;
        __syncthreads();
        if (kt + 16 < DIN) {
            ra = *(const float4*)(xp + kt + 16);
            rb = *(const float4*)(Ap + kt + 16);
        }
        #pragma unroll
        for (int k = 0; k < 16; ++k) {
            float4 av = *(const float4*)&As[k][ty];
            const u64* bq = (const u64*)&Bs[k][tx];
            u64 b0 = bq[0], b1 = bq[1];
            float a[4] = {av.x, av.y, av.z, av.w};
            #pragma unroll
            for (int i = 0; i < 4; ++i) {
                u64 a2 = pack2(a[i], a[i]);
                fma2(acc[i][0], a2, b0);
                fma2(acc[i][1], a2, b1);
            }
        }
        __syncthreads();
    }

    #pragma unroll
    for (int i = 0; i < 4; ++i) {
        float v0, v1, v2, v3;
        unpack2(acc[i][0], v0, v1);
        unpack2(acc[i][1], v2, v3);
        zt[ty+i][tx+0] = v0; zt[ty+i][tx+1] = v1;
        zt[ty+i][tx+2] = v2; zt[ty+i][tx+3] = v3;
    }
    __syncthreads();

    // warp-parallel soft top-k: warp w handles rows w*8..w*8+7, one at a time.
    {
        const int wid  = tid >> 5;
        const int lane = tid & 31;
        for (int rr = 0; rr < 8; ++rr) {
            const int row = wid * 8 + rr;
            const float v0 = zt[row][lane];
            const float v1 = zt[row][lane + 32];
            const float a0 = fabsf(v0), a1 = fabsf(v1);
            float x0 = a0, x1 = a1;
            float thr = 0.0f;
            #pragma unroll
            for (int t = 0; t < KTOP; ++t) {
                float m = fmaxf(x0, x1);
                #pragma unroll
                for (int o = 16; o > 0; o >>= 1)
                    m = fmaxf(m, __shfl_xor_sync(0xffffffffu, m, o));
                thr = m;
                // remove exactly one instance of the max (tie-exact, matches top_k)
                unsigned ball = __ballot_sync(0xffffffffu, (x0 == m) || (x1 == m));
                int leader = __ffs(ball) - 1;
                if (lane == leader) {
                    if (x0 == m) x0 = -1.0f; else x1 = -1.0f;
                }
            }
            const float m0 = 1.0f / (1.0f + expf((thr - a0) * 10.0f));
            const float m1 = 1.0f / (1.0f + expf((thr - a1) * 10.0f));
            float* zo = g_z + (size_t)(row0 + row) * RNK;
            zo[lane]      = v0 * m0;
            zo[lane + 32] = v1 * m1;
        }
    }
}

// ---------------------------------------------------------------------------
// Kernel 2: tf32 mma.sync GEMM, CTA 128x128, warp 64x32, BK=32, 2-stage smem.
// LoRA fused as K-chunks 128..129 sourcing g_z / B.
// ---------------------------------------------------------------------------
__global__ __launch_bounds__(256, 1) void tf32_gemm_kernel(
    const float* __restrict__ x, const float* __restrict__ W,
    const float* __restrict__ Bm, const float* __restrict__ bias,
    float* __restrict__ out)
{
    extern __shared__ __align__(16) char sm[];

    const int tid  = threadIdx.x;
    const int lane = tid & 31;
    const int wid  = tid >> 5;
    const int wm   = wid >> 2;           // 0..1  (M half of CTA)
    const int wn   = wid & 3;            // 0..3  (N quarter)
    const int row0 = blockIdx.y * BM;
    const int col0 = blockIdx.x * BN;

    // loader geometry: thread covers (row lrow & lrow+64, k-slice ls) of A and B
    const int lrow = tid >> 2;           // 0..63
    const int ls   = tid & 3;            // slice (8 k each)

    const float* xA0 = x   + (size_t)(row0 + lrow) * DIN + ls * 8;
    const float* xA1 = xA0 + (size_t)64 * DIN;
    const float* wB0 = W   + (size_t)(col0 + lrow) * DIN + ls * 8;
    const float* wB1 = wB0 + (size_t)64 * DIN;
    const float* zA0 = g_z + (size_t)(row0 + lrow) * RNK + ls * 8;
    const float* zA1 = zA0 + (size_t)64 * RNK;
    const float* bB0 = Bm  + (size_t)(col0 + lrow) * RNK + ls * 8;
    const float* bB1 = bB0 + (size_t)64 * RNK;

    uint4 Ra0, Ra0h, Ra1, Ra1h, Rb0, Rb0h, Rb1, Rb1h;  // lo = k0..3, h = k4..7

    #define LOAD_TILE(it) do {                                                  \
        if ((it) < KCHUNKS) {                                                   \
            const size_t ko = (size_t)(it) * BK;                                \
            Ra0  = *(const uint4*)(xA0 + ko); Ra0h = *(const uint4*)(xA0 + ko + 4); \
            Ra1  = *(const uint4*)(xA1 + ko); Ra1h = *(const uint4*)(xA1 + ko + 4); \
            Rb0  = *(const uint4*)(wB0 + ko); Rb0h = *(const uint4*)(wB0 + ko + 4); \
            Rb1  = *(const uint4*)(wB1 + ko); Rb1h = *(const uint4*)(wB1 + ko + 4); \
        } else {                                                                \
            const size_t ko = (size_t)((it) - KCHUNKS) * BK;                    \
            Ra0  = *(const uint4*)(zA0 + ko); Ra0h = *(const uint4*)(zA0 + ko + 4); \
            Ra1  = *(const uint4*)(zA1 + ko); Ra1h = *(const uint4*)(zA1 + ko + 4); \
            Rb0  = *(const uint4*)(bB0 + ko); Rb0h = *(const uint4*)(bB0 + ko + 4); \
            Rb1  = *(const uint4*)(bB1 + ko); Rb1h = *(const uint4*)(bB1 + ko + 4); \
        }                                                                       \
    } while (0)

    // smem store of one (row, slice) unit: 4 k-pairs (k, k+4) as float2
    #define STS_UNIT(base, r, lo, hi) do {                                      \
        char* p_ = (base) + (size_t)(r) * ROWB;                                 \
        *(float2*)(p_ +  0) = rnd2((lo).x, (hi).x);                             \
        *(float2*)(p_ +  8) = rnd2((lo).y, (hi).y);                             \
        *(float2*)(p_ + 16) = rnd2((lo).z, (hi).z);                             \
        *(float2*)(p_ + 24) = rnd2((lo).w, (hi).w);                             \
    } while (0)

    #define STS_TILE(buf) do {                                                  \
        char* Ab_ = sm + (buf) * STAGEB + ls * SLICEB;                          \
        char* Bb_ = Ab_ + REGB;                                                 \
        STS_UNIT(Ab_, lrow,      Ra0, Ra0h);                                    \
        STS_UNIT(Ab_, lrow + 64, Ra1, Ra1h);                                    \
        STS_UNIT(Bb_, lrow,      Rb0, Rb0h);                                    \
        STS_UNIT(Bb_, lrow + 64, Rb1, Rb1h);                                    \
    } while (0)

    float acc[4][4][4];
    #pragma unroll
    for (int i = 0; i < 4; ++i)
        #pragma unroll
        for (int j = 0; j < 4; ++j)
            #pragma unroll
            for (int q = 0; q < 4; ++q) acc[i][j][q] = 0.0f;

    LOAD_TILE(0);
    STS_TILE(0);
    __syncthreads();

    for (int it = 0; it < NITER; ++it) {
        const int nxt = it + 1;
        if (nxt < NITER) LOAD_TILE(nxt);

        // compute from stage it&1
        {
            const char* Ab = sm + (it & 1) * STAGEB;
            const char* Bb = Ab + REGB;
            const int ar = wm * 64 + (lane >> 2);
            const int br = wn * 32 + (lane >> 2);
            const int cp = (lane & 3) * 8;
            #pragma unroll
            for (int s = 0; s < 4; ++s) {
                const char* ab = Ab + s * SLICEB + ar * ROWB + cp;
                const char* bb = Bb + s * SLICEB + br * ROWB + cp;
                float2 afr[4][2], bfr[4];
                #pragma unroll
                for (int mi = 0; mi < 4; ++mi) {
                    afr[mi][0] = *(const float2*)(ab + mi * (16 * ROWB));
                    afr[mi][1] = *(const float2*)(ab + mi * (16 * ROWB) + 8 * ROWB);
                }
                #pragma unroll
                for (int nj = 0; nj < 4; ++nj)
                    bfr[nj] = *(const float2*)(bb + nj * (8 * ROWB));
                #pragma unroll
                for (int mi = 0; mi < 4; ++mi)
                    #pragma unroll
                    for (int nj = 0; nj < 4; ++nj)
                        mma16818(acc[mi][nj], afr[mi][0], afr[mi][1], bfr[nj]);
            }
        }

        if (nxt < NITER) STS_TILE(nxt & 1);
        __syncthreads();
    }

    // epilogue: + bias, float2 stores
    #pragma unroll
    for (int mi = 0; mi < 4; ++mi) {
        const int r = row0 + wm * 64 + mi * 16 + (lane >> 2);
        #pragma unroll
        for (int nj = 0; nj < 4; ++nj) {
            const int c = col0 + wn * 32 + nj * 8 + (lane & 3) * 2;
            const float2 bv = *(const float2*)&bias[c];
            float2 o0, o1;
            o0.x = acc[mi][nj][0] + bv.x;  o0.y = acc[mi][nj][1] + bv.y;
            o1.x = acc[mi][nj][2] + bv.x;  o1.y = acc[mi][nj][3] + bv.y;
            *(float2*)&out[(size_t)r * DOUT + c]       = o0;
            *(float2*)&out[(size_t)(r + 8) * DOUT + c] = o1;
        }
    }
}

// ---------------------------------------------------------------------------
extern "C" void kernel_launch(void* const* d_in, const int* in_sizes, int n_in,
                              void* d_out, int out_size)
{
    const float* x    = (const float*)d_in[0];   // [8192, 4096]
    const float* A    = (const float*)d_in[1];   // [64, 4096]
    const float* Bm   = (const float*)d_in[2];   // [4096, 64]
    const float* W    = (const float*)d_in[3];   // [4096, 4096]
    const float* bias = (const float*)d_in[4];   // [4096]
    float* out = (float*)d_out;                  // [8192, 4096]

    lora_z_topk_kernel<<<MROWS / 64, 256>>>(x, A);

    cudaFuncSetAttribute(tf32_gemm_kernel,
                         cudaFuncAttributeMaxDynamicSharedMemorySize, SMEMB);
    dim3 grid(DOUT / BN, MROWS / BM);   // (32, 64) = 2048 CTAs
    tf32_gemm_kernel<<<grid, 256, SMEMB>>>(x, W, Bm, bias, out);
}

// round 4
// speedup vs baseline: 3.2192x; 1.6970x over previous
#include <cuda_runtime.h>
#include <cstdint>

// FixedTopKLoRALinear — Round 4: tf32 mma.sync + cp.async pipeline,
// pre-rounded/permuted operands, conflict-free smem swizzle, warp tile 64x64.
//   out = x @ W^T + bias + soft_topk(x @ A^T) @ B^T    (SCALE = 1.0)
// x[8192,4096] W[4096,4096] A[64,4096] B[4096,64] bias[4096], all fp32.

typedef unsigned long long u64;

#define DIN   4096
#define DOUT  4096
#define MROWS 8192
#define RNK   64
#define KTOP  16

// ---- GEMM tiling ----
#define BM 128
#define BN 256
#define BK 32
#define KCHUNKS (DIN / BK)                 // 128
#define NITER   (KCHUNKS + RNK / BK)       // 130
#define STAGES  3
#define SA_BYTES (BM * 128)                // 16384  (BM rows x 32 tf32)
#define SB_BYTES (BN * 128)                // 32768
#define STG_BYTES (SA_BYTES + SB_BYTES)    // 49152
#define SMEMB (STAGES * STG_BYTES)         // 147456

// pre-rounded, column-permuted operands (permute within each 8-col group:
// phys p holds logical k = (p&1)*4 + (p>>1)  ->  8B chunk = (k, k+4) pair)
__device__ float g_x32[(size_t)MROWS * DIN];   // 128 MB
__device__ float g_w32[(size_t)DOUT * DIN];    //  64 MB
__device__ float g_b32[(size_t)DOUT * RNK];    //   1 MB
__device__ float g_z  [(size_t)MROWS * RNK];   //   2 MB (kernel1 output, rounded+permuted)

// ---------------------------------------------------------------------------
// helpers
// ---------------------------------------------------------------------------
__device__ __forceinline__ float rnd1(float v) {            // fp32 -> tf32 RN
    return __uint_as_float(__float_as_uint(v) + 0x1000u);
}
__device__ __forceinline__ uint32_t smem_u32(const void* p) {
    uint32_t a;
    asm("{ .reg .u64 t; cvta.to.shared.u64 t, %1; cvt.u32.u64 %0, t; }"
        : "=r"(a) : "l"(p));
    return a;
}
__device__ __forceinline__ void cpa16(uint32_t dst, const void* src) {
    asm volatile("cp.async.cg.shared.global [%0], [%1], 16;" :: "r"(dst), "l"(src));
}
__device__ __forceinline__ void cp_commit() {
    asm volatile("cp.async.commit_group;" ::: "memory");
}
__device__ __forceinline__ void cp_wait1() {
    asm volatile("cp.async.wait_group 1;" ::: "memory");
}
// m16n8k8 tf32 mma. a02 = (a0,a2), a13 = (a1,a3), b01 = (b0,b1)
__device__ __forceinline__ void mma16818(float* d, float2 a02, float2 a13, float2 b01) {
    asm("mma.sync.aligned.m16n8k8.row.col.f32.tf32.tf32.f32 "
        "{%0,%1,%2,%3}, {%4,%5,%6,%7}, {%8,%9}, {%0,%1,%2,%3};"
        : "+f"(d[0]), "+f"(d[1]), "+f"(d[2]), "+f"(d[3])
        : "r"(__float_as_uint(a02.x)), "r"(__float_as_uint(a13.x)),
          "r"(__float_as_uint(a02.y)), "r"(__float_as_uint(a13.y)),
          "r"(__float_as_uint(b01.x)), "r"(__float_as_uint(b01.y)));
}
__device__ __forceinline__ u64 pack2(float lo, float hi) {
    u64 r; asm("mov.b64 %0, {%1, %2};" : "=l"(r) : "f"(lo), "f"(hi)); return r;
}
__device__ __forceinline__ void unpack2(u64 v, float& lo, float& hi) {
    asm("mov.b64 {%0, %1}, %2;" : "=f"(lo), "=f"(hi) : "l"(v));
}
__device__ __forceinline__ void fma2(u64& acc, u64 a, u64 b) {
    asm("fma.rn.f32x2 %0, %1, %2, %0;" : "+l"(acc) : "l"(a), "l"(b));
}

// ---------------------------------------------------------------------------
// Prep: round-to-tf32 + permute each 8-col group (k0,k4,k1,k5,k2,k6,k3,k7)
// ---------------------------------------------------------------------------
__global__ __launch_bounds__(256) void prep_kernel(
    const float* __restrict__ in, float* __restrict__ out, int n8)
{
    int i = blockIdx.x * blockDim.x + threadIdx.x;
    if (i >= n8) return;
    const float4* p = (const float4*)(in + (size_t)i * 8);
    float4 a = p[0], b = p[1];          // logical k0..3, k4..7
    float4 o0, o1;
    o0.x = rnd1(a.x); o0.y = rnd1(b.x); o0.z = rnd1(a.y); o0.w = rnd1(b.y);
    o1.x = rnd1(a.z); o1.y = rnd1(b.z); o1.z = rnd1(a.w); o1.w = rnd1(b.w);
    float4* q = (float4*)(out + (size_t)i * 8);
    q[0] = o0; q[1] = o1;
}

// ---------------------------------------------------------------------------
// Kernel 1: z = x @ A^T, exact 16th-largest-|z| threshold, sigmoid soft mask.
// Output written rounded + permuted (ready for mma B/A-side consumption).
// ---------------------------------------------------------------------------
__global__ __launch_bounds__(256) void lora_z_topk_kernel(
    const float* __restrict__ x, const float* __restrict__ A)
{
    __shared__ __align__(16) float As[16][64];
    __shared__ __align__(16) float Bs[16][64];
    __shared__ float zt[64][65];

    const int tid  = threadIdx.x;
    const int row0 = blockIdx.x * 64;
    const int tx   = (tid & 15) * 4;
    const int ty   = (tid >> 4) * 4;
    const int lr   = tid >> 2;
    const int lc   = (tid & 3) * 4;

    const float* xp = x + (size_t)(row0 + lr) * DIN + lc;
    const float* Ap = A + (size_t)lr * DIN + lc;

    u64 acc[4][2];
    #pragma unroll
    for (int i = 0; i < 4; ++i) { acc[i][0] = 0ull; acc[i][1] = 0ull; }

    float4 ra = *(const float4*)xp;
    float4 rb = *(const float4*)Ap;

    for (int kt = 0; kt < DIN; kt += 16) {
        As[lc+0][lr] = ra.x; As[lc+1][lr] = ra.y; As[lc+2][lr] = ra.z; As[lc+3][lr] = ra.w;
        Bs[lc+0][lr] = rb.x; Bs[lc+1][lr] = rb.y; Bs[lc+2][lr] = rb.z; Bs[lc+3][lr] = rb.w;
        __syncthreads();
        if (kt + 16 < DIN) {
            ra = *(const float4*)(xp + kt + 16);
            rb = *(const float4*)(Ap + kt + 16);
        }
        #pragma unroll
        for (int k = 0; k < 16; ++k) {
            float4 av = *(const float4*)&As[k][ty];
            const u64* bq = (const u64*)&Bs[k][tx];
            u64 b0 = bq[0], b1 = bq[1];
            float a[4] = {av.x, av.y, av.z, av.w};
            #pragma unroll
            for (int i = 0; i < 4; ++i) {
                u64 a2 = pack2(a[i], a[i]);
                fma2(acc[i][0], a2, b0);
                fma2(acc[i][1], a2, b1);
            }
        }
        __syncthreads();
    }

    #pragma unroll
    for (int i = 0; i < 4; ++i) {
        float v0, v1, v2, v3;
        unpack2(acc[i][0], v0, v1);
        unpack2(acc[i][1], v2, v3);
        zt[ty+i][tx+0] = v0; zt[ty+i][tx+1] = v1;
        zt[ty+i][tx+2] = v2; zt[ty+i][tx+3] = v3;
    }
    __syncthreads();

    // warp-parallel soft top-k; write rounded + permuted
    {
        const int wid  = tid >> 5;
        const int lane = tid & 31;
        // permuted indices for logical cols lane, lane+32
        const int j0 = lane,      l0 = j0 & 7;
        const int j1 = lane + 32, l1 = j1 & 7;
        const int p0 = (j0 >> 3) * 8 + (((l0 & 3) << 1) | (l0 >> 2));
        const int p1 = (j1 >> 3) * 8 + (((l1 & 3) << 1) | (l1 >> 2));
        for (int rr = 0; rr < 8; ++rr) {
            const int row = wid * 8 + rr;
            const float v0 = zt[row][lane];
            const float v1 = zt[row][lane + 32];
            const float a0 = fabsf(v0), a1 = fabsf(v1);
            float x0 = a0, x1 = a1;
            float thr = 0.0f;
            #pragma unroll
            for (int t = 0; t < KTOP; ++t) {
                float m = fmaxf(x0, x1);
                #pragma unroll
                for (int o = 16; o > 0; o >>= 1)
                    m = fmaxf(m, __shfl_xor_sync(0xffffffffu, m, o));
                thr = m;
                unsigned ball = __ballot_sync(0xffffffffu, (x0 == m) || (x1 == m));
                int leader = __ffs(ball) - 1;
                if (lane == leader) {
                    if (x0 == m) x0 = -1.0f; else x1 = -1.0f;
                }
            }
            const float m0 = 1.0f / (1.0f + expf((thr - a0) * 10.0f));
            const float m1 = 1.0f / (1.0f + expf((thr - a1) * 10.0f));
            float* zo = g_z + (size_t)(row0 + row) * RNK;
            zo[p0] = rnd1(v0 * m0);
            zo[p1] = rnd1(v1 * m1);
        }
    }
}

// ---------------------------------------------------------------------------
// Kernel 2: tf32 mma.sync GEMM. CTA 128x256, 8 warps (2x4), warp 64x64, BK=32.
// cp.async 3-stage pipeline from pre-rounded/permuted gmem.
// smem row = 128B (4 k8-slices x 32B); slice swizzled: phys = (s + row)&3.
// LoRA fused as iters 128..129 sourcing g_z / g_b32.
// ---------------------------------------------------------------------------
__global__ __launch_bounds__(256, 1) void tf32_gemm_kernel(
    const float* __restrict__ bias, float* __restrict__ out)
{
    extern __shared__ __align__(16) char sm[];
    const uint32_t sA = smem_u32(sm);

    const int tid  = threadIdx.x;
    const int lane = tid & 31;
    const int wid  = tid >> 5;
    const int wm   = wid >> 2;            // 0..1
    const int wn   = wid & 3;             // 0..3
    const int row0 = blockIdx.y * BM;
    const int col0 = blockIdx.x * BN;

    // ---- loader geometry: lr = row-in-32-group, lc = 16B chunk (0..7) ----
    const int lr = tid >> 3;              // 0..31
    const int lc = tid & 7;
    // conflict-free dst swizzle (constant: (lr+32j)&3 == lr&3)
    const uint32_t swd = ((((lc >> 1) + (lr & 3)) & 3) * 32) + (lc & 1) * 16;
    const uint32_t dA = (uint32_t)lr * 128 + swd;
    const uint32_t dB = dA;               // same formula, B region offset added later

    const float* pAx = g_x32 + (size_t)(row0 + lr) * DIN + lc * 4;
    const float* pBw = g_w32 + (size_t)(col0 + lr) * DIN + lc * 4;
    const float* pAz = g_z   + (size_t)(row0 + lr) * RNK + lc * 4;
    const float* pBb = g_b32 + (size_t)(col0 + lr) * RNK + lc * 4;

    #define ISSUE(nit) do {                                                     \
        if ((nit) < NITER) {                                                    \
            const uint32_t sb = sA + ((nit) % STAGES) * STG_BYTES;              \
            if ((nit) < KCHUNKS) {                                              \
                const float* a0 = pAx + (size_t)(nit) * BK;                     \
                const float* b0 = pBw + (size_t)(nit) * BK;                     \
                _Pragma("unroll")                                               \
                for (int j = 0; j < 4; ++j)                                     \
                    cpa16(sb + dA + j * (32 * 128), a0 + (size_t)j * 32 * DIN); \
                _Pragma("unroll")                                               \
                for (int j = 0; j < 8; ++j)                                     \
                    cpa16(sb + SA_BYTES + dB + j * (32 * 128), b0 + (size_t)j * 32 * DIN); \
            } else {                                                            \
                const float* a0 = pAz + (size_t)((nit) - KCHUNKS) * BK;         \
                const float* b0 = pBb + (size_t)((nit) - KCHUNKS) * BK;         \
                _Pragma("unroll")                                               \
                for (int j = 0; j < 4; ++j)                                     \
                    cpa16(sb + dA + j * (32 * 128), a0 + (size_t)j * 32 * RNK); \
                _Pragma("unroll")                                               \
                for (int j = 0; j < 8; ++j)                                     \
                    cpa16(sb + SA_BYTES + dB + j * (32 * 128), b0 + (size_t)j * 32 * RNK); \
            }                                                                   \
        }                                                                       \
        cp_commit();                                                            \
    } while (0)

    float acc[4][8][4];
    #pragma unroll
    for (int i = 0; i < 4; ++i)
        #pragma unroll
        for (int j = 0; j < 8; ++j)
            #pragma unroll
            for (int q = 0; q < 4; ++q) acc[i][j][q] = 0.0f;

    // fragment addressing (constant parts)
    const int g = lane >> 2;              // 0..7
    const int c = lane & 3;               // kpair
    // A: rows wm*64 + mi*16 + g (+8);  B: rows wn*64 + nj*8 + g
    const char* smc = sm;

    ISSUE(0);
    ISSUE(1);

    for (int it = 0; it < NITER; ++it) {
        cp_wait1();
        __syncthreads();
        ISSUE(it + 2);

        const char* Ab = smc + (it % STAGES) * STG_BYTES;
        const char* Bb = Ab + SA_BYTES;
        const char* aBase = Ab + (size_t)(wm * 64 + g) * 128 + c * 8;
        const char* bBase = Bb + (size_t)(wn * 64 + g) * 128 + c * 8;

        #pragma unroll
        for (int s = 0; s < 4; ++s) {
            const int sw = ((s + g) & 3) * 32;
            float2 af[4][2], bf[8];
            #pragma unroll
            for (int mi = 0; mi < 4; ++mi) {
                af[mi][0] = *(const float2*)(aBase + mi * (16 * 128) + sw);
                af[mi][1] = *(const float2*)(aBase + mi * (16 * 128) + 8 * 128 + sw);
            }
            #pragma unroll
            for (int nj = 0; nj < 8; ++nj)
                bf[nj] = *(const float2*)(bBase + nj * (8 * 128) + sw);
            #pragma unroll
            for (int mi = 0; mi < 4; ++mi)
                #pragma unroll
                for (int nj = 0; nj < 8; ++nj)
                    mma16818(acc[mi][nj], af[mi][0], af[mi][1], bf[nj]);
        }
        __syncthreads();
    }

    // epilogue: + bias, float2 stores
    #pragma unroll
    for (int mi = 0; mi < 4; ++mi) {
        const int r = row0 + wm * 64 + mi * 16 + g;
        #pragma unroll
        for (int nj = 0; nj < 8; ++nj) {
            const int cg = col0 + wn * 64 + nj * 8 + c * 2;
            const float2 bv = *(const float2*)&bias[cg];
            float2 o0, o1;
            o0.x = acc[mi][nj][0] + bv.x;  o0.y = acc[mi][nj][1] + bv.y;
            o1.x = acc[mi][nj][2] + bv.x;  o1.y = acc[mi][nj][3] + bv.y;
            *(float2*)&out[(size_t)r * DOUT + cg]       = o0;
            *(float2*)&out[(size_t)(r + 8) * DOUT + cg] = o1;
        }
    }
}

// ---------------------------------------------------------------------------
extern "C" void kernel_launch(void* const* d_in, const int* in_sizes, int n_in,
                              void* d_out, int out_size)
{
    const float* x    = (const float*)d_in[0];   // [8192, 4096]
    const float* A    = (const float*)d_in[1];   // [64, 4096]
    const float* Bm   = (const float*)d_in[2];   // [4096, 64]
    const float* W    = (const float*)d_in[3];   // [4096, 4096]
    const float* bias = (const float*)d_in[4];   // [4096]
    float* out = (float*)d_out;                  // [8192, 4096]

    float* xp; cudaGetSymbolAddress((void**)&xp, g_x32);
    float* wp; cudaGetSymbolAddress((void**)&wp, g_w32);
    float* bp; cudaGetSymbolAddress((void**)&bp, g_b32);

    // prep: round + permute
    {
        int n8x = MROWS * DIN / 8;
        int n8w = DOUT * DIN / 8;
        int n8b = DOUT * RNK / 8;
        prep_kernel<<<(n8x + 255) / 256, 256>>>(x,  xp, n8x);
        prep_kernel<<<(n8w + 255) / 256, 256>>>(W,  wp, n8w);
        prep_kernel<<<(n8b + 255) / 256, 256>>>(Bm, bp, n8b);
    }

    lora_z_topk_kernel<<<MROWS / 64, 256>>>(x, A);

    cudaFuncSetAttribute(tf32_gemm_kernel,
                         cudaFuncAttributeMaxDynamicSharedMemorySize, SMEMB);
    dim3 grid(DOUT / BN, MROWS / BM);   // (16, 64) = 1024 CTAs
    tf32_gemm_kernel<<<grid, 256, SMEMB>>>(bias, out);
}

// round 5
// speedup vs baseline: 3.3328x; 1.0353x over previous
#include <cuda_runtime.h>
#include <cstdint>

// FixedTopKLoRALinear — Round 5: split-K kernel1 + 4-stage single-sync GEMM.
//   out = x @ W^T + bias + soft_topk(x @ A^T) @ B^T    (SCALE = 1.0)
// x[8192,4096] W[4096,4096] A[64,4096] B[4096,64] bias[4096], all fp32.

typedef unsigned long long u64;

#define DIN   4096
#define DOUT  4096
#define MROWS 8192
#define RNK   64
#define KTOP  16
#define KSPLIT 4
#define KSEG  (DIN / KSPLIT)               // 1024

// ---- GEMM tiling ----
#define BM 128
#define BN 256
#define BK 32
#define KCHUNKS (DIN / BK)                 // 128
#define NITER   (KCHUNKS + RNK / BK)       // 130
#define STAGES  4
#define SA_BYTES (BM * 128)                // 16384
#define SB_BYTES (BN * 128)                // 32768
#define STG_BYTES (SA_BYTES + SB_BYTES)    // 49152
#define SMEMB (STAGES * STG_BYTES)         // 196608

// pre-rounded, column-permuted operands (permute within each 8-col group:
// phys p holds logical k = (p&1)*4 + (p>>1)  ->  8B chunk = (k, k+4) pair)
__device__ float g_x32[(size_t)MROWS * DIN];   // 128 MB
__device__ float g_w32[(size_t)DOUT * DIN];    //  64 MB
__device__ float g_b32[(size_t)DOUT * RNK];    //   1 MB
__device__ float g_z  [(size_t)MROWS * RNK];   //   2 MB (rounded+permuted z_sparse)
__device__ float g_zp [(size_t)KSPLIT * MROWS * RNK];  // 8 MB split-K partials

// ---------------------------------------------------------------------------
// helpers
// ---------------------------------------------------------------------------
__device__ __forceinline__ float rnd1(float v) {            // fp32 -> tf32 RN
    return __uint_as_float(__float_as_uint(v) + 0x1000u);
}
__device__ __forceinline__ uint32_t smem_u32(const void* p) {
    uint32_t a;
    asm("{ .reg .u64 t; cvta.to.shared.u64 t, %1; cvt.u32.u64 %0, t; }"
        : "=r"(a) : "l"(p));
    return a;
}
__device__ __forceinline__ void cpa16(uint32_t dst, const void* src) {
    asm volatile("cp.async.cg.shared.global [%0], [%1], 16;" :: "r"(dst), "l"(src));
}
__device__ __forceinline__ void cp_commit() {
    asm volatile("cp.async.commit_group;" ::: "memory");
}
__device__ __forceinline__ void cp_wait2() {
    asm volatile("cp.async.wait_group 2;" ::: "memory");
}
// m16n8k8 tf32 mma
__device__ __forceinline__ void mma16818(float* d, float2 a02, float2 a13, float2 b01) {
    asm("mma.sync.aligned.m16n8k8.row.col.f32.tf32.tf32.f32 "
        "{%0,%1,%2,%3}, {%4,%5,%6,%7}, {%8,%9}, {%0,%1,%2,%3};"
        : "+f"(d[0]), "+f"(d[1]), "+f"(d[2]), "+f"(d[3])
        : "r"(__float_as_uint(a02.x)), "r"(__float_as_uint(a13.x)),
          "r"(__float_as_uint(a02.y)), "r"(__float_as_uint(a13.y)),
          "r"(__float_as_uint(b01.x)), "r"(__float_as_uint(b01.y)));
}
__device__ __forceinline__ u64 pack2(float lo, float hi) {
    u64 r; asm("mov.b64 %0, {%1, %2};" : "=l"(r) : "f"(lo), "f"(hi)); return r;
}
__device__ __forceinline__ void unpack2(u64 v, float& lo, float& hi) {
    asm("mov.b64 {%0, %1}, %2;" : "=f"(lo), "=f"(hi) : "l"(v));
}
__device__ __forceinline__ void fma2(u64& acc, u64 a, u64 b) {
    asm("fma.rn.f32x2 %0, %1, %2, %0;" : "+l"(acc) : "l"(a), "l"(b));
}

// ---------------------------------------------------------------------------
// Prep: round-to-tf32 + permute each 8-col group (k0,k4,k1,k5,k2,k6,k3,k7)
// ---------------------------------------------------------------------------
__global__ __launch_bounds__(256) void prep_kernel(
    const float* __restrict__ in, float* __restrict__ out, int n8)
{
    int i = blockIdx.x * blockDim.x + threadIdx.x;
    if (i >= n8) return;
    const float4* p = (const float4*)(in + (size_t)i * 8);
    float4 a = p[0], b = p[1];
    float4 o0, o1;
    o0.x = rnd1(a.x); o0.y = rnd1(b.x); o0.z = rnd1(a.y); o0.w = rnd1(b.y);
    o1.x = rnd1(a.z); o1.y = rnd1(b.z); o1.z = rnd1(a.w); o1.w = rnd1(b.w);
    float4* q = (float4*)(out + (size_t)i * 8);
    q[0] = o0; q[1] = o1;
}

// ---------------------------------------------------------------------------
// Kernel 1a: split-K partial z = x[:, seg] @ A[:, seg]^T  (64 rows x 64 ranks)
// grid = (MROWS/64, KSPLIT).  Deterministic: fixed segment per blockIdx.y.
// ---------------------------------------------------------------------------
__global__ __launch_bounds__(256) void lora_z_partial_kernel(
    const float* __restrict__ x, const float* __restrict__ A)
{
    __shared__ __align__(16) float As[16][64];
    __shared__ __align__(16) float Bs[16][64];

    const int tid  = threadIdx.x;
    const int row0 = blockIdx.x * 64;
    const int ks   = blockIdx.y;
    const int klo  = ks * KSEG;
    const int tx   = (tid & 15) * 4;
    const int ty   = (tid >> 4) * 4;
    const int lr   = tid >> 2;
    const int lc   = (tid & 3) * 4;

    const float* xp = x + (size_t)(row0 + lr) * DIN + klo + lc;
    const float* Ap = A + (size_t)lr * DIN + klo + lc;

    u64 acc[4][2];
    #pragma unroll
    for (int i = 0; i < 4; ++i) { acc[i][0] = 0ull; acc[i][1] = 0ull; }

    float4 ra = *(const float4*)xp;
    float4 rb = *(const float4*)Ap;

    for (int kt = 0; kt < KSEG; kt += 16) {
        As[lc+0][lr] = ra.x; As[lc+1][lr] = ra.y; As[lc+2][lr] = ra.z; As[lc+3][lr] = ra.w;
        Bs[lc+0][lr] = rb.x; Bs[lc+1][lr] = rb.y; Bs[lc+2][lr] = rb.z; Bs[lc+3][lr] = rb.w;
        __syncthreads();
        if (kt + 16 < KSEG) {
            ra = *(const float4*)(xp + kt + 16);
            rb = *(const float4*)(Ap + kt + 16);
        }
        #pragma unroll
        for (int k = 0; k < 16; ++k) {
            float4 av = *(const float4*)&As[k][ty];
            const u64* bq = (const u64*)&Bs[k][tx];
            u64 b0 = bq[0], b1 = bq[1];
            float a[4] = {av.x, av.y, av.z, av.w};
            #pragma unroll
            for (int i = 0; i < 4; ++i) {
                u64 a2 = pack2(a[i], a[i]);
                fma2(acc[i][0], a2, b0);
                fma2(acc[i][1], a2, b1);
            }
        }
        __syncthreads();
    }

    float* zp = g_zp + (size_t)ks * MROWS * RNK;
    #pragma unroll
    for (int i = 0; i < 4; ++i) {
        float v0, v1, v2, v3;
        unpack2(acc[i][0], v0, v1);
        unpack2(acc[i][1], v2, v3);
        float4 o = make_float4(v0, v1, v2, v3);
        *(float4*)&zp[(size_t)(row0 + ty + i) * RNK + tx] = o;
    }
}

// ---------------------------------------------------------------------------
// Kernel 1b: reduce partials + exact soft top-k, write rounded+permuted g_z.
// grid = MROWS/64, block = 256 (8 warps x 8 rows).
// ---------------------------------------------------------------------------
__global__ __launch_bounds__(256) void lora_topk_kernel()
{
    const int tid  = threadIdx.x;
    const int wid  = tid >> 5;
    const int lane = tid & 31;
    const int row0 = blockIdx.x * 64;

    const int j0 = lane,      l0 = j0 & 7;
    const int j1 = lane + 32, l1 = j1 & 7;
    const int p0 = (j0 >> 3) * 8 + (((l0 & 3) << 1) | (l0 >> 2));
    const int p1 = (j1 >> 3) * 8 + (((l1 & 3) << 1) | (l1 >> 2));

    for (int rr = 0; rr < 8; ++rr) {
        const int row = row0 + wid * 8 + rr;
        const size_t base = (size_t)row * RNK;
        float v0 = 0.0f, v1 = 0.0f;
        #pragma unroll
        for (int s = 0; s < KSPLIT; ++s) {
            const float* zp = g_zp + (size_t)s * MROWS * RNK + base;
            v0 += zp[lane];
            v1 += zp[lane + 32];
        }
        const float a0 = fabsf(v0), a1 = fabsf(v1);
        float x0 = a0, x1 = a1;
        float thr = 0.0f;
        #pragma unroll
        for (int t = 0; t < KTOP; ++t) {
            float m = fmaxf(x0, x1);
            #pragma unroll
            for (int o = 16; o > 0; o >>= 1)
                m = fmaxf(m, __shfl_xor_sync(0xffffffffu, m, o));
            thr = m;
            unsigned ball = __ballot_sync(0xffffffffu, (x0 == m) || (x1 == m));
            int leader = __ffs(ball) - 1;
            if (lane == leader) {
                if (x0 == m) x0 = -1.0f; else x1 = -1.0f;
            }
        }
        const float m0 = 1.0f / (1.0f + expf((thr - a0) * 10.0f));
        const float m1 = 1.0f / (1.0f + expf((thr - a1) * 10.0f));
        g_z[base + p0] = rnd1(v0 * m0);
        g_z[base + p1] = rnd1(v1 * m1);
    }
}

// ---------------------------------------------------------------------------
// Kernel 2: tf32 mma.sync GEMM. CTA 128x256, warp 64x64, BK=32,
// 4-stage cp.async pipeline, ONE __syncthreads per iteration.
// LoRA fused as iters 128..129 sourcing g_z / g_b32.
// ---------------------------------------------------------------------------
__global__ __launch_bounds__(256, 1) void tf32_gemm_kernel(
    const float* __restrict__ bias, float* __restrict__ out)
{
    extern __shared__ __align__(16) char sm[];
    const uint32_t sA = smem_u32(sm);

    const int tid  = threadIdx.x;
    const int lane = tid & 31;
    const int wid  = tid >> 5;
    const int wm   = wid >> 2;            // 0..1
    const int wn   = wid & 3;             // 0..3
    const int row0 = blockIdx.y * BM;
    const int col0 = blockIdx.x * BN;

    const int lr = tid >> 3;              // 0..31
    const int lc = tid & 7;
    const uint32_t swd = ((((lc >> 1) + (lr & 3)) & 3) * 32) + (lc & 1) * 16;
    const uint32_t dA = (uint32_t)lr * 128 + swd;

    const float* pAx = g_x32 + (size_t)(row0 + lr) * DIN + lc * 4;
    const float* pBw = g_w32 + (size_t)(col0 + lr) * DIN + lc * 4;
    const float* pAz = g_z   + (size_t)(row0 + lr) * RNK + lc * 4;
    const float* pBb = g_b32 + (size_t)(col0 + lr) * RNK + lc * 4;

    #define ISSUE(nit) do {                                                     \
        if ((nit) < NITER) {                                                    \
            const uint32_t sb = sA + ((nit) & (STAGES - 1)) * STG_BYTES;        \
            if ((nit) < KCHUNKS) {                                              \
                const float* a0 = pAx + (size_t)(nit) * BK;                     \
                const float* b0 = pBw + (size_t)(nit) * BK;                     \
                _Pragma("unroll")                                               \
                for (int j = 0; j < 4; ++j)                                     \
                    cpa16(sb + dA + j * (32 * 128), a0 + (size_t)j * 32 * DIN); \
                _Pragma("unroll")                                               \
                for (int j = 0; j < 8; ++j)                                     \
                    cpa16(sb + SA_BYTES + dA + j * (32 * 128), b0 + (size_t)j * 32 * DIN); \
            } else {                                                            \
                const float* a0 = pAz + (size_t)((nit) - KCHUNKS) * BK;         \
                const float* b0 = pBb + (size_t)((nit) - KCHUNKS) * BK;         \
                _Pragma("unroll")                                               \
                for (int j = 0; j < 4; ++j)                                     \
                    cpa16(sb + dA + j * (32 * 128), a0 + (size_t)j * 32 * RNK); \
                _Pragma("unroll")                                               \
                for (int j = 0; j < 8; ++j)                                     \
                    cpa16(sb + SA_BYTES + dA + j * (32 * 128), b0 + (size_t)j * 32 * RNK); \
            }                                                                   \
        }                                                                       \
        cp_commit();                                                            \
    } while (0)

    float acc[4][8][4];
    #pragma unroll
    for (int i = 0; i < 4; ++i)
        #pragma unroll
        for (int j = 0; j < 8; ++j)
            #pragma unroll
            for (int q = 0; q < 4; ++q) acc[i][j][q] = 0.0f;

    const int g = lane >> 2;              // 0..7
    const int c = lane & 3;
    const char* smc = sm;

    ISSUE(0);
    ISSUE(1);
    ISSUE(2);

    for (int it = 0; it < NITER; ++it) {
        cp_wait2();
        __syncthreads();
        // overwrites stage (it-1)&3: all warps proved past iter it-1 compute
        // by the barrier above -> single sync per iteration is safe.
        ISSUE(it + 3);

        const char* Ab = smc + (it & (STAGES - 1)) * STG_BYTES;
        const char* Bb = Ab + SA_BYTES;
        const char* aBase = Ab + (size_t)(wm * 64 + g) * 128 + c * 8;
        const char* bBase = Bb + (size_t)(wn * 64 + g) * 128 + c * 8;

        #pragma unroll
        for (int s = 0; s < 4; ++s) {
            const int sw = ((s + g) & 3) * 32;
            float2 af[4][2], bf[8];
            #pragma unroll
            for (int mi = 0; mi < 4; ++mi) {
                af[mi][0] = *(const float2*)(aBase + mi * (16 * 128) + sw);
                af[mi][1] = *(const float2*)(aBase + mi * (16 * 128) + 8 * 128 + sw);
            }
            #pragma unroll
            for (int nj = 0; nj < 8; ++nj)
                bf[nj] = *(const float2*)(bBase + nj * (8 * 128) + sw);
            #pragma unroll
            for (int mi = 0; mi < 4; ++mi)
                #pragma unroll
                for (int nj = 0; nj < 8; ++nj)
                    mma16818(acc[mi][nj], af[mi][0], af[mi][1], bf[nj]);
        }
    }

    // epilogue: + bias, float2 stores
    #pragma unroll
    for (int mi = 0; mi < 4; ++mi) {
        const int r = row0 + wm * 64 + mi * 16 + g;
        #pragma unroll
        for (int nj = 0; nj < 8; ++nj) {
            const int cg = col0 + wn * 64 + nj * 8 + c * 2;
            const float2 bv = *(const float2*)&bias[cg];
            float2 o0, o1;
            o0.x = acc[mi][nj][0] + bv.x;  o0.y = acc[mi][nj][1] + bv.y;
            o1.x = acc[mi][nj][2] + bv.x;  o1.y = acc[mi][nj][3] + bv.y;
            *(float2*)&out[(size_t)r * DOUT + cg]       = o0;
            *(float2*)&out[(size_t)(r + 8) * DOUT + cg] = o1;
        }
    }
}

// ---------------------------------------------------------------------------
extern "C" void kernel_launch(void* const* d_in, const int* in_sizes, int n_in,
                              void* d_out, int out_size)
{
    const float* x    = (const float*)d_in[0];   // [8192, 4096]
    const float* A    = (const float*)d_in[1];   // [64, 4096]
    const float* Bm   = (const float*)d_in[2];   // [4096, 64]
    const float* W    = (const float*)d_in[3];   // [4096, 4096]
    const float* bias = (const float*)d_in[4];   // [4096]
    float* out = (float*)d_out;                  // [8192, 4096]

    float* xp; cudaGetSymbolAddress((void**)&xp, g_x32);
    float* wp; cudaGetSymbolAddress((void**)&wp, g_w32);
    float* bp; cudaGetSymbolAddress((void**)&bp, g_b32);

    {
        int n8x = MROWS * DIN / 8;
        int n8w = DOUT * DIN / 8;
        int n8b = DOUT * RNK / 8;
        prep_kernel<<<(n8x + 255) / 256, 256>>>(x,  xp, n8x);
        prep_kernel<<<(n8w + 255) / 256, 256>>>(W,  wp, n8w);
        prep_kernel<<<(n8b + 255) / 256, 256>>>(Bm, bp, n8b);
    }

    {
        dim3 gz(MROWS / 64, KSPLIT);
        lora_z_partial_kernel<<<gz, 256>>>(x, A);
        lora_topk_kernel<<<MROWS / 64, 256>>>();
    }

    cudaFuncSetAttribute(tf32_gemm_kernel,
                         cudaFuncAttributeMaxDynamicSharedMemorySize, SMEMB);
    dim3 grid(DOUT / BN, MROWS / BM);   // (16, 64) = 1024 CTAs
    tf32_gemm_kernel<<<grid, 256, SMEMB>>>(bias, out);
}

// round 6
// speedup vs baseline: 3.5899x; 1.0771x over previous
#include <cuda_runtime.h>
#include <cstdint>

// FixedTopKLoRALinear — Round 6: kernel-1 on tensor cores (split-K mma),
// permute removed (same-k-permutation trick), prep = tf32 rounding only.
//   out = x @ W^T + bias + soft_topk(x @ A^T) @ B^T    (SCALE = 1.0)
// x[8192,4096] W[4096,4096] A[64,4096] B[4096,64] bias[4096], all fp32.

typedef unsigned long long u64;

#define DIN   4096
#define DOUT  4096
#define MROWS 8192
#define RNK   64
#define KTOP  16
#define KSPL  8
#define KSEG  (DIN / KSPL)                 // 512

// ---- main GEMM tiling ----
#define BM 128
#define BN 256
#define BK 32
#define KCHUNKS (DIN / BK)                 // 128
#define NITER   (KCHUNKS + RNK / BK)       // 130
#define STAGES  4
#define SA_BYTES (BM * 128)                // 16384
#define SB_BYTES (BN * 128)                // 32768
#define STG_BYTES (SA_BYTES + SB_BYTES)    // 49152
#define SMEMB (STAGES * STG_BYTES)         // 196608

// ---- kernel-1 GEMM tiling (CTA 128x64, K-seg 512, BK=32, 16 iters) ----
#define Z_SA (128 * 128)                   // 16384
#define Z_SB (64 * 128)                    // 8192
#define Z_STG (Z_SA + Z_SB)                // 24576
#define Z_SMEM (STAGES * Z_STG)            // 98304
#define Z_ITERS (KSEG / BK)                // 16

// tf32-rounded operands (natural column order; mma fragments use the same
// implicit k-permutation on A and B sides, so no data permute is needed)
__device__ float g_x32[(size_t)MROWS * DIN];   // 128 MB
__device__ float g_w32[(size_t)DOUT * DIN];    //  64 MB
__device__ float g_b32[(size_t)DOUT * RNK];    //   1 MB
__device__ float g_a32[(size_t)RNK * DIN];     //   1 MB
__device__ float g_z  [(size_t)MROWS * RNK];   //   2 MB (rounded z_sparse)
__device__ float g_zp [(size_t)KSPL * MROWS * RNK];  // 16 MB split-K partials

// ---------------------------------------------------------------------------
// helpers
// ---------------------------------------------------------------------------
__device__ __forceinline__ float rnd1(float v) {            // fp32 -> tf32 RN
    return __uint_as_float(__float_as_uint(v) + 0x1000u);
}
__device__ __forceinline__ uint32_t smem_u32(const void* p) {
    uint32_t a;
    asm("{ .reg .u64 t; cvta.to.shared.u64 t, %1; cvt.u32.u64 %0, t; }"
        : "=r"(a) : "l"(p));
    return a;
}
__device__ __forceinline__ void cpa16(uint32_t dst, const void* src) {
    asm volatile("cp.async.cg.shared.global [%0], [%1], 16;" :: "r"(dst), "l"(src));
}
__device__ __forceinline__ void cp_commit() {
    asm volatile("cp.async.commit_group;" ::: "memory");
}
__device__ __forceinline__ void cp_wait2() {
    asm volatile("cp.async.wait_group 2;" ::: "memory");
}
// m16n8k8 tf32 mma
__device__ __forceinline__ void mma16818(float* d, float2 a02, float2 a13, float2 b01) {
    asm("mma.sync.aligned.m16n8k8.row.col.f32.tf32.tf32.f32 "
        "{%0,%1,%2,%3}, {%4,%5,%6,%7}, {%8,%9}, {%0,%1,%2,%3};"
        : "+f"(d[0]), "+f"(d[1]), "+f"(d[2]), "+f"(d[3])
        : "r"(__float_as_uint(a02.x)), "r"(__float_as_uint(a13.x)),
          "r"(__float_as_uint(a02.y)), "r"(__float_as_uint(a13.y)),
          "r"(__float_as_uint(b01.x)), "r"(__float_as_uint(b01.y)));
}

// ---------------------------------------------------------------------------
// Prep: tf32 round-to-nearest, 4 floats / thread
// ---------------------------------------------------------------------------
__global__ __launch_bounds__(256) void prep_kernel(
    const float* __restrict__ in, float* __restrict__ out, int n4)
{
    int i = blockIdx.x * blockDim.x + threadIdx.x;
    if (i >= n4) return;
    float4 a = ((const float4*)in)[i];
    a.x = rnd1(a.x); a.y = rnd1(a.y); a.z = rnd1(a.z); a.w = rnd1(a.w);
    ((float4*)out)[i] = a;
}

// ---------------------------------------------------------------------------
// Kernel 1a: split-K partial z = x[:, seg] @ A[:, seg]^T via mma.sync.
// grid (MROWS/128, KSPL) = (64, 8). CTA 128x64, warp tile 32x32 (4x2 warps).
// Reads pre-rounded g_x32 / g_a32.
// ---------------------------------------------------------------------------
__global__ __launch_bounds__(256, 2) void lora_z_mma_kernel()
{
    extern __shared__ __align__(16) char sm[];
    const uint32_t sA = smem_u32(sm);

    const int tid  = threadIdx.x;
    const int lane = tid & 31;
    const int wid  = tid >> 5;
    const int wm   = wid >> 1;            // 0..3 (32-row group)
    const int wn   = wid & 1;             // 0..1 (32-col group)
    const int row0 = blockIdx.x * 128;
    const int ks   = blockIdx.y;
    const int kbase = ks * KSEG;

    const int lr = tid >> 3;              // 0..31
    const int lc = tid & 7;
    const uint32_t swd = ((((lc >> 1) + (lr & 3)) & 3) * 32) + (lc & 1) * 16;
    const uint32_t dA = (uint32_t)lr * 128 + swd;

    const float* pX = g_x32 + (size_t)(row0 + lr) * DIN + kbase + lc * 4;
    const float* pA = g_a32 + (size_t)lr * DIN + kbase + lc * 4;

    #define Z_ISSUE(nit) do {                                                  \
        if ((nit) < Z_ITERS) {                                                 \
            const uint32_t sb = sA + ((nit) & (STAGES - 1)) * Z_STG;            \
            const float* a0 = pX + (size_t)(nit) * BK;                         \
            const float* b0 = pA + (size_t)(nit) * BK;                         \
            _Pragma("unroll")                                                  \
            for (int j = 0; j < 4; ++j)                                        \
                cpa16(sb + dA + j * (32 * 128), a0 + (size_t)j * 32 * DIN);    \
            _Pragma("unroll")                                                  \
            for (int j = 0; j < 2; ++j)                                        \
                cpa16(sb + Z_SA + dA + j * (32 * 128), b0 + (size_t)j * 32 * DIN); \
        }                                                                      \
        cp_commit();                                                           \
    } while (0)

    float acc[2][4][4];
    #pragma unroll
    for (int i = 0; i < 2; ++i)
        #pragma unroll
        for (int j = 0; j < 4; ++j)
            #pragma unroll
            for (int q = 0; q < 4; ++q) acc[i][j][q] = 0.0f;

    const int g = lane >> 2;
    const int c = lane & 3;
    const char* smc = sm;

    Z_ISSUE(0);
    Z_ISSUE(1);
    Z_ISSUE(2);

    for (int it = 0; it < Z_ITERS; ++it) {
        cp_wait2();
        __syncthreads();
        Z_ISSUE(it + 3);

        const char* Ab = smc + (it & (STAGES - 1)) * Z_STG;
        const char* Bb = Ab + Z_SA;
        const char* aBase = Ab + (size_t)(wm * 32 + g) * 128 + c * 8;
        const char* bBase = Bb + (size_t)(wn * 32 + g) * 128 + c * 8;

        #pragma unroll
        for (int s = 0; s < 4; ++s) {
            const int sw = ((s + g) & 3) * 32;
            float2 af[2][2], bf[4];
            #pragma unroll
            for (int mi = 0; mi < 2; ++mi) {
                af[mi][0] = *(const float2*)(aBase + mi * (16 * 128) + sw);
                af[mi][1] = *(const float2*)(aBase + mi * (16 * 128) + 8 * 128 + sw);
            }
            #pragma unroll
            for (int nj = 0; nj < 4; ++nj)
                bf[nj] = *(const float2*)(bBase + nj * (8 * 128) + sw);
            #pragma unroll
            for (int mi = 0; mi < 2; ++mi)
                #pragma unroll
                for (int nj = 0; nj < 4; ++nj)
                    mma16818(acc[mi][nj], af[mi][0], af[mi][1], bf[nj]);
        }
    }

    float* zp = g_zp + (size_t)ks * MROWS * RNK;
    #pragma unroll
    for (int mi = 0; mi < 2; ++mi) {
        const int r = row0 + wm * 32 + mi * 16 + g;
        #pragma unroll
        for (int nj = 0; nj < 4; ++nj) {
            const int cg = wn * 32 + nj * 8 + c * 2;
            float2 o0, o1;
            o0.x = acc[mi][nj][0]; o0.y = acc[mi][nj][1];
            o1.x = acc[mi][nj][2]; o1.y = acc[mi][nj][3];
            *(float2*)&zp[(size_t)r * RNK + cg]       = o0;
            *(float2*)&zp[(size_t)(r + 8) * RNK + cg] = o1;
        }
    }
}

// ---------------------------------------------------------------------------
// Kernel 1b: reduce 8 partials + exact soft top-k, write rounded g_z.
// ---------------------------------------------------------------------------
__global__ __launch_bounds__(256) void lora_topk_kernel()
{
    const int tid  = threadIdx.x;
    const int wid  = tid >> 5;
    const int lane = tid & 31;
    const int row0 = blockIdx.x * 64;

    for (int rr = 0; rr < 8; ++rr) {
        const int row = row0 + wid * 8 + rr;
        const size_t base = (size_t)row * RNK;
        float v0 = 0.0f, v1 = 0.0f;
        #pragma unroll
        for (int s = 0; s < KSPL; ++s) {
            const float* zp = g_zp + (size_t)s * MROWS * RNK + base;
            v0 += zp[lane];
            v1 += zp[lane + 32];
        }
        const float a0 = fabsf(v0), a1 = fabsf(v1);
        float x0 = a0, x1 = a1;
        float thr = 0.0f;
        #pragma unroll
        for (int t = 0; t < KTOP; ++t) {
            float m = fmaxf(x0, x1);
            #pragma unroll
            for (int o = 16; o > 0; o >>= 1)
                m = fmaxf(m, __shfl_xor_sync(0xffffffffu, m, o));
            thr = m;
            unsigned ball = __ballot_sync(0xffffffffu, (x0 == m) || (x1 == m));
            int leader = __ffs(ball) - 1;
            if (lane == leader) {
                if (x0 == m) x0 = -1.0f; else x1 = -1.0f;
            }
        }
        const float m0 = 1.0f / (1.0f + expf((thr - a0) * 10.0f));
        const float m1 = 1.0f / (1.0f + expf((thr - a1) * 10.0f));
        g_z[base + lane]      = rnd1(v0 * m0);
        g_z[base + lane + 32] = rnd1(v1 * m1);
    }
}

// ---------------------------------------------------------------------------
// Kernel 2: tf32 mma.sync GEMM. CTA 128x256, warp 64x64, BK=32,
// 4-stage cp.async pipeline, one __syncthreads per iteration.
// LoRA fused as iters 128..129 sourcing g_z / g_b32.
// ---------------------------------------------------------------------------
__global__ __launch_bounds__(256, 1) void tf32_gemm_kernel(
    const float* __restrict__ bias, float* __restrict__ out)
{
    extern __shared__ __align__(16) char sm[];
    const uint32_t sA = smem_u32(sm);

    const int tid  = threadIdx.x;
    const int lane = tid & 31;
    const int wid  = tid >> 5;
    const int wm   = wid >> 2;            // 0..1
    const int wn   = wid & 3;             // 0..3
    const int row0 = blockIdx.y * BM;
    const int col0 = blockIdx.x * BN;

    const int lr = tid >> 3;              // 0..31
    const int lc = tid & 7;
    const uint32_t swd = ((((lc >> 1) + (lr & 3)) & 3) * 32) + (lc & 1) * 16;
    const uint32_t dA = (uint32_t)lr * 128 + swd;

    const float* pAx = g_x32 + (size_t)(row0 + lr) * DIN + lc * 4;
    const float* pBw = g_w32 + (size_t)(col0 + lr) * DIN + lc * 4;
    const float* pAz = g_z   + (size_t)(row0 + lr) * RNK + lc * 4;
    const float* pBb = g_b32 + (size_t)(col0 + lr) * RNK + lc * 4;

    #define ISSUE(nit) do {                                                     \
        if ((nit) < NITER) {                                                    \
            const uint32_t sb = sA + ((nit) & (STAGES - 1)) * STG_BYTES;        \
            if ((nit) < KCHUNKS) {                                              \
                const float* a0 = pAx + (size_t)(nit) * BK;                     \
                const float* b0 = pBw + (size_t)(nit) * BK;                     \
                _Pragma("unroll")                                               \
                for (int j = 0; j < 4; ++j)                                     \
                    cpa16(sb + dA + j * (32 * 128), a0 + (size_t)j * 32 * DIN); \
                _Pragma("unroll")                                               \
                for (int j = 0; j < 8; ++j)                                     \
                    cpa16(sb + SA_BYTES + dA + j * (32 * 128), b0 + (size_t)j * 32 * DIN); \
            } else {                                                            \
                const float* a0 = pAz + (size_t)((nit) - KCHUNKS) * BK;         \
                const float* b0 = pBb + (size_t)((nit) - KCHUNKS) * BK;         \
                _Pragma("unroll")                                               \
                for (int j = 0; j < 4; ++j)                                     \
                    cpa16(sb + dA + j * (32 * 128), a0 + (size_t)j * 32 * RNK); \
                _Pragma("unroll")                                               \
                for (int j = 0; j < 8; ++j)                                     \
                    cpa16(sb + SA_BYTES + dA + j * (32 * 128), b0 + (size_t)j * 32 * RNK); \
            }                                                                   \
        }                                                                       \
        cp_commit();                                                            \
    } while (0)

    float acc[4][8][4];
    #pragma unroll
    for (int i = 0; i < 4; ++i)
        #pragma unroll
        for (int j = 0; j < 8; ++j)
            #pragma unroll
            for (int q = 0; q < 4; ++q) acc[i][j][q] = 0.0f;

    const int g = lane >> 2;
    const int c = lane & 3;
    const char* smc = sm;

    ISSUE(0);
    ISSUE(1);
    ISSUE(2);

    for (int it = 0; it < NITER; ++it) {
        cp_wait2();
        __syncthreads();
        ISSUE(it + 3);

        const char* Ab = smc + (it & (STAGES - 1)) * STG_BYTES;
        const char* Bb = Ab + SA_BYTES;
        const char* aBase = Ab + (size_t)(wm * 64 + g) * 128 + c * 8;
        const char* bBase = Bb + (size_t)(wn * 64 + g) * 128 + c * 8;

        #pragma unroll
        for (int s = 0; s < 4; ++s) {
            const int sw = ((s + g) & 3) * 32;
            float2 af[4][2], bf[8];
            #pragma unroll
            for (int mi = 0; mi < 4; ++mi) {
                af[mi][0] = *(const float2*)(aBase + mi * (16 * 128) + sw);
                af[mi][1] = *(const float2*)(aBase + mi * (16 * 128) + 8 * 128 + sw);
            }
            #pragma unroll
            for (int nj = 0; nj < 8; ++nj)
                bf[nj] = *(const float2*)(bBase + nj * (8 * 128) + sw);
            #pragma unroll
            for (int mi = 0; mi < 4; ++mi)
                #pragma unroll
                for (int nj = 0; nj < 8; ++nj)
                    mma16818(acc[mi][nj], af[mi][0], af[mi][1], bf[nj]);
        }
    }

    #pragma unroll
    for (int mi = 0; mi < 4; ++mi) {
        const int r = row0 + wm * 64 + mi * 16 + g;
        #pragma unroll
        for (int nj = 0; nj < 8; ++nj) {
            const int cg = col0 + wn * 64 + nj * 8 + c * 2;
            const float2 bv = *(const float2*)&bias[cg];
            float2 o0, o1;
            o0.x = acc[mi][nj][0] + bv.x;  o0.y = acc[mi][nj][1] + bv.y;
            o1.x = acc[mi][nj][2] + bv.x;  o1.y = acc[mi][nj][3] + bv.y;
            *(float2*)&out[(size_t)r * DOUT + cg]       = o0;
            *(float2*)&out[(size_t)(r + 8) * DOUT + cg] = o1;
        }
    }
}

// ---------------------------------------------------------------------------
extern "C" void kernel_launch(void* const* d_in, const int* in_sizes, int n_in,
                              void* d_out, int out_size)
{
    const float* x    = (const float*)d_in[0];   // [8192, 4096]
    const float* A    = (const float*)d_in[1];   // [64, 4096]
    const float* Bm   = (const float*)d_in[2];   // [4096, 64]
    const float* W    = (const float*)d_in[3];   // [4096, 4096]
    const float* bias = (const float*)d_in[4];   // [4096]
    float* out = (float*)d_out;                  // [8192, 4096]

    float* xp; cudaGetSymbolAddress((void**)&xp, g_x32);
    float* wp; cudaGetSymbolAddress((void**)&wp, g_w32);
    float* bp; cudaGetSymbolAddress((void**)&bp, g_b32);
    float* ap; cudaGetSymbolAddress((void**)&ap, g_a32);

    {
        int n4x = MROWS * DIN / 4;
        int n4w = DOUT * DIN / 4;
        int n4b = DOUT * RNK / 4;
        int n4a = RNK * DIN / 4;
        prep_kernel<<<(n4x + 255) / 256, 256>>>(x,  xp, n4x);
        prep_kernel<<<(n4w + 255) / 256, 256>>>(W,  wp, n4w);
        prep_kernel<<<(n4b + 255) / 256, 256>>>(Bm, bp, n4b);
        prep_kernel<<<(n4a + 255) / 256, 256>>>(A,  ap, n4a);
    }

    cudaFuncSetAttribute(lora_z_mma_kernel,
                         cudaFuncAttributeMaxDynamicSharedMemorySize, Z_SMEM);
    {
        dim3 gz(MROWS / 128, KSPL);   // (64, 8)
        lora_z_mma_kernel<<<gz, 256, Z_SMEM>>>();
        lora_topk_kernel<<<MROWS / 64, 256>>>();
    }

    cudaFuncSetAttribute(tf32_gemm_kernel,
                         cudaFuncAttributeMaxDynamicSharedMemorySize, SMEMB);
    dim3 grid(DOUT / BN, MROWS / BM);   // (16, 64) = 1024 CTAs
    tf32_gemm_kernel<<<grid, 256, SMEMB>>>(bias, out);
}

// round 7
// speedup vs baseline: 3.7521x; 1.0452x over previous
#include <cuda_runtime.h>
#include <cstdint>

// FixedTopKLoRALinear — Round 7: GEMM restructured to BK=64 / 2-stage /
// fragment-double-buffered inner loop (65 iters, one sync each).
//   out = x @ W^T + bias + soft_topk(x @ A^T) @ B^T    (SCALE = 1.0)
// x[8192,4096] W[4096,4096] A[64,4096] B[4096,64] bias[4096], all fp32.

typedef unsigned long long u64;

#define DIN   4096
#define DOUT  4096
#define MROWS 8192
#define RNK   64
#define KTOP  16
#define KSPL  8
#define KSEG  (DIN / KSPL)                 // 512

// ---- main GEMM tiling ----
#define BM 128
#define BN 256
#define BKH 32                             // half-K (sub-tile)
#define BK  64
#define KCH64 (DIN / BK)                   // 64
#define NIT64 (KCH64 + 1)                  // 65 (last iter = LoRA, RNK=64)
#define SA_BYTES (BM * 128)                // 16384 (per sub-tile)
#define SB_BYTES (BN * 128)                // 32768
#define SUB_BYTES (SA_BYTES + SB_BYTES)    // 49152
#define STG2_BYTES (2 * SUB_BYTES)         // 98304 per stage
#define SMEMB (2 * STG2_BYTES)             // 196608

// ---- kernel-1 GEMM tiling (CTA 128x64, K-seg 512, BK=32, 16 iters) ----
#define ZSTAGES 4
#define Z_SA (128 * 128)                   // 16384
#define Z_SB (64 * 128)                    // 8192
#define Z_STG (Z_SA + Z_SB)                // 24576
#define Z_SMEM (ZSTAGES * Z_STG)           // 98304
#define Z_ITERS (KSEG / BKH)               // 16

// tf32-rounded operands (natural column order)
__device__ float g_x32[(size_t)MROWS * DIN];   // 128 MB
__device__ float g_w32[(size_t)DOUT * DIN];    //  64 MB
__device__ float g_b32[(size_t)DOUT * RNK];    //   1 MB
__device__ float g_a32[(size_t)RNK * DIN];     //   1 MB
__device__ float g_z  [(size_t)MROWS * RNK];   //   2 MB
__device__ float g_zp [(size_t)KSPL * MROWS * RNK];  // 16 MB

// ---------------------------------------------------------------------------
// helpers
// ---------------------------------------------------------------------------
__device__ __forceinline__ float rnd1(float v) {            // fp32 -> tf32 RN
    return __uint_as_float(__float_as_uint(v) + 0x1000u);
}
__device__ __forceinline__ uint32_t smem_u32(const void* p) {
    uint32_t a;
    asm("{ .reg .u64 t; cvta.to.shared.u64 t, %1; cvt.u32.u64 %0, t; }"
        : "=r"(a) : "l"(p));
    return a;
}
__device__ __forceinline__ void cpa16(uint32_t dst, const void* src) {
    asm volatile("cp.async.cg.shared.global [%0], [%1], 16;" :: "r"(dst), "l"(src));
}
__device__ __forceinline__ void cp_commit() {
    asm volatile("cp.async.commit_group;" ::: "memory");
}
__device__ __forceinline__ void cp_wait0() {
    asm volatile("cp.async.wait_group 0;" ::: "memory");
}
__device__ __forceinline__ void cp_wait2() {
    asm volatile("cp.async.wait_group 2;" ::: "memory");
}
__device__ __forceinline__ void mma16818(float* d, float2 a02, float2 a13, float2 b01) {
    asm("mma.sync.aligned.m16n8k8.row.col.f32.tf32.tf32.f32 "
        "{%0,%1,%2,%3}, {%4,%5,%6,%7}, {%8,%9}, {%0,%1,%2,%3};"
        : "+f"(d[0]), "+f"(d[1]), "+f"(d[2]), "+f"(d[3])
        : "r"(__float_as_uint(a02.x)), "r"(__float_as_uint(a13.x)),
          "r"(__float_as_uint(a02.y)), "r"(__float_as_uint(a13.y)),
          "r"(__float_as_uint(b01.x)), "r"(__float_as_uint(b01.y)));
}

// ---------------------------------------------------------------------------
// Prep: tf32 round-to-nearest, 4 floats / thread
// ---------------------------------------------------------------------------
__global__ __launch_bounds__(256) void prep_kernel(
    const float* __restrict__ in, float* __restrict__ out, int n4)
{
    int i = blockIdx.x * blockDim.x + threadIdx.x;
    if (i >= n4) return;
    float4 a = ((const float4*)in)[i];
    a.x = rnd1(a.x); a.y = rnd1(a.y); a.z = rnd1(a.z); a.w = rnd1(a.w);
    ((float4*)out)[i] = a;
}

// ---------------------------------------------------------------------------
// Kernel 1a: split-K partial z = x[:, seg] @ A[:, seg]^T via mma.sync.
// (unchanged from validated round-6 version)
// ---------------------------------------------------------------------------
__global__ __launch_bounds__(256, 2) void lora_z_mma_kernel()
{
    extern __shared__ __align__(16) char sm[];
    const uint32_t sA = smem_u32(sm);

    const int tid  = threadIdx.x;
    const int lane = tid & 31;
    const int wid  = tid >> 5;
    const int wm   = wid >> 1;
    const int wn   = wid & 1;
    const int row0 = blockIdx.x * 128;
    const int ks   = blockIdx.y;
    const int kbase = ks * KSEG;

    const int lr = tid >> 3;
    const int lc = tid & 7;
    const uint32_t swd = ((((lc >> 1) + (lr & 3)) & 3) * 32) + (lc & 1) * 16;
    const uint32_t dA = (uint32_t)lr * 128 + swd;

    const float* pX = g_x32 + (size_t)(row0 + lr) * DIN + kbase + lc * 4;
    const float* pA = g_a32 + (size_t)lr * DIN + kbase + lc * 4;

    #define Z_ISSUE(nit) do {                                                  \
        if ((nit) < Z_ITERS) {                                                 \
            const uint32_t sb = sA + ((nit) & (ZSTAGES - 1)) * Z_STG;           \
            const float* a0 = pX + (size_t)(nit) * BKH;                        \
            const float* b0 = pA + (size_t)(nit) * BKH;                        \
            _Pragma("unroll")                                                  \
            for (int j = 0; j < 4; ++j)                                        \
                cpa16(sb + dA + j * (32 * 128), a0 + (size_t)j * 32 * DIN);    \
            _Pragma("unroll")                                                  \
            for (int j = 0; j < 2; ++j)                                        \
                cpa16(sb + Z_SA + dA + j * (32 * 128), b0 + (size_t)j * 32 * DIN); \
        }                                                                      \
        cp_commit();                                                           \
    } while (0)

    float acc[2][4][4];
    #pragma unroll
    for (int i = 0; i < 2; ++i)
        #pragma unroll
        for (int j = 0; j < 4; ++j)
            #pragma unroll
            for (int q = 0; q < 4; ++q) acc[i][j][q] = 0.0f;

    const int g = lane >> 2;
    const int c = lane & 3;
    const char* smc = sm;

    Z_ISSUE(0);
    Z_ISSUE(1);
    Z_ISSUE(2);

    for (int it = 0; it < Z_ITERS; ++it) {
        cp_wait2();
        __syncthreads();
        Z_ISSUE(it + 3);

        const char* Ab = smc + (it & (ZSTAGES - 1)) * Z_STG;
        const char* Bb = Ab + Z_SA;
        const char* aBase = Ab + (size_t)(wm * 32 + g) * 128 + c * 8;
        const char* bBase = Bb + (size_t)(wn * 32 + g) * 128 + c * 8;

        #pragma unroll
        for (int s = 0; s < 4; ++s) {
            const int sw = ((s + g) & 3) * 32;
            float2 af[2][2], bf[4];
            #pragma unroll
            for (int mi = 0; mi < 2; ++mi) {
                af[mi][0] = *(const float2*)(aBase + mi * (16 * 128) + sw);
                af[mi][1] = *(const float2*)(aBase + mi * (16 * 128) + 8 * 128 + sw);
            }
            #pragma unroll
            for (int nj = 0; nj < 4; ++nj)
                bf[nj] = *(const float2*)(bBase + nj * (8 * 128) + sw);
            #pragma unroll
            for (int mi = 0; mi < 2; ++mi)
                #pragma unroll
                for (int nj = 0; nj < 4; ++nj)
                    mma16818(acc[mi][nj], af[mi][0], af[mi][1], bf[nj]);
        }
    }

    float* zp = g_zp + (size_t)ks * MROWS * RNK;
    #pragma unroll
    for (int mi = 0; mi < 2; ++mi) {
        const int r = row0 + wm * 32 + mi * 16 + g;
        #pragma unroll
        for (int nj = 0; nj < 4; ++nj) {
            const int cg = wn * 32 + nj * 8 + c * 2;
            float2 o0, o1;
            o0.x = acc[mi][nj][0]; o0.y = acc[mi][nj][1];
            o1.x = acc[mi][nj][2]; o1.y = acc[mi][nj][3];
            *(float2*)&zp[(size_t)r * RNK + cg]       = o0;
            *(float2*)&zp[(size_t)(r + 8) * RNK + cg] = o1;
        }
    }
}

// ---------------------------------------------------------------------------
// Kernel 1b: reduce 8 partials + exact soft top-k, write rounded g_z.
// ---------------------------------------------------------------------------
__global__ __launch_bounds__(256) void lora_topk_kernel()
{
    const int tid  = threadIdx.x;
    const int wid  = tid >> 5;
    const int lane = tid & 31;
    const int row0 = blockIdx.x * 64;

    for (int rr = 0; rr < 8; ++rr) {
        const int row = row0 + wid * 8 + rr;
        const size_t base = (size_t)row * RNK;
        float v0 = 0.0f, v1 = 0.0f;
        #pragma unroll
        for (int s = 0; s < KSPL; ++s) {
            const float* zp = g_zp + (size_t)s * MROWS * RNK + base;
            v0 += zp[lane];
            v1 += zp[lane + 32];
        }
        const float a0 = fabsf(v0), a1 = fabsf(v1);
        float x0 = a0, x1 = a1;
        float thr = 0.0f;
        #pragma unroll
        for (int t = 0; t < KTOP; ++t) {
            float m = fmaxf(x0, x1);
            #pragma unroll
            for (int o = 16; o > 0; o >>= 1)
                m = fmaxf(m, __shfl_xor_sync(0xffffffffu, m, o));
            thr = m;
            unsigned ball = __ballot_sync(0xffffffffu, (x0 == m) || (x1 == m));
            int leader = __ffs(ball) - 1;
            if (lane == leader) {
                if (x0 == m) x0 = -1.0f; else x1 = -1.0f;
            }
        }
        const float m0 = 1.0f / (1.0f + expf((thr - a0) * 10.0f));
        const float m1 = 1.0f / (1.0f + expf((thr - a1) * 10.0f));
        g_z[base + lane]      = rnd1(v0 * m0);
        g_z[base + lane + 32] = rnd1(v1 * m1);
    }
}

// ---------------------------------------------------------------------------
// Kernel 2: tf32 mma.sync GEMM. CTA 128x256, warp 64x64, BK=64 (2 sub-tiles),
// 2-stage cp.async pipeline, fragment double buffering, one sync per iter.
// Iter 64 = LoRA (g_z / g_b32, RNK=64).
// ---------------------------------------------------------------------------
__global__ __launch_bounds__(256, 1) void tf32_gemm_kernel(
    const float* __restrict__ bias, float* __restrict__ out)
{
    extern __shared__ __align__(16) char sm[];
    const uint32_t sA = smem_u32(sm);

    const int tid  = threadIdx.x;
    const int lane = tid & 31;
    const int wid  = tid >> 5;
    const int wm   = wid >> 2;            // 0..1
    const int wn   = wid & 3;             // 0..3
    const int row0 = blockIdx.y * BM;
    const int col0 = blockIdx.x * BN;

    const int lr = tid >> 3;              // 0..31
    const int lc = tid & 7;
    const uint32_t swd = ((((lc >> 1) + (lr & 3)) & 3) * 32) + (lc & 1) * 16;
    const uint32_t dA = (uint32_t)lr * 128 + swd;

    const float* pAx = g_x32 + (size_t)(row0 + lr) * DIN + lc * 4;
    const float* pBw = g_w32 + (size_t)(col0 + lr) * DIN + lc * 4;
    const float* pAz = g_z   + (size_t)(row0 + lr) * RNK + lc * 4;
    const float* pBb = g_b32 + (size_t)(col0 + lr) * RNK + lc * 4;

    // one ISSUE = full BK=64 iter = 2 sub-tiles, 24 cp.async/thread
    #define ISSUE(nit) do {                                                     \
        if ((nit) < NIT64) {                                                    \
            const uint32_t sb = sA + ((nit) & 1) * STG2_BYTES;                  \
            if ((nit) < KCH64) {                                                \
                _Pragma("unroll")                                               \
                for (int sub = 0; sub < 2; ++sub) {                             \
                    const uint32_t st = sb + sub * SUB_BYTES;                   \
                    const float* a0 = pAx + (size_t)(nit) * BK + sub * BKH;     \
                    const float* b0 = pBw + (size_t)(nit) * BK + sub * BKH;     \
                    _Pragma("unroll")                                           \
                    for (int j = 0; j < 4; ++j)                                 \
                        cpa16(st + dA + j * (32 * 128), a0 + (size_t)j * 32 * DIN); \
                    _Pragma("unroll")                                           \
                    for (int j = 0; j < 8; ++j)                                 \
                        cpa16(st + SA_BYTES + dA + j * (32 * 128), b0 + (size_t)j * 32 * DIN); \
                }                                                               \
            } else {                                                            \
                _Pragma("unroll")                                               \
                for (int sub = 0; sub < 2; ++sub) {                             \
                    const uint32_t st = sb + sub * SUB_BYTES;                   \
                    const float* a0 = pAz + sub * BKH;                          \
                    const float* b0 = pBb + sub * BKH;                          \
                    _Pragma("unroll")                                           \
                    for (int j = 0; j < 4; ++j)                                 \
                        cpa16(st + dA + j * (32 * 128), a0 + (size_t)j * 32 * RNK); \
                    _Pragma("unroll")                                           \
                    for (int j = 0; j < 8; ++j)                                 \
                        cpa16(st + SA_BYTES + dA + j * (32 * 128), b0 + (size_t)j * 32 * RNK); \
                }                                                               \
            }                                                                   \
        }                                                                       \
        cp_commit();                                                            \
    } while (0)

    float acc[4][8][4];
    #pragma unroll
    for (int i = 0; i < 4; ++i)
        #pragma unroll
        for (int j = 0; j < 8; ++j)
            #pragma unroll
            for (int q = 0; q < 4; ++q) acc[i][j][q] = 0.0f;

    const int g = lane >> 2;
    const int c = lane & 3;
    const char* smc = sm;

    ISSUE(0);

    for (int it = 0; it < NIT64; ++it) {
        cp_wait0();
        __syncthreads();
        ISSUE(it + 1);          // fills opposite stage while we compute

        const char* stg = smc + (it & 1) * STG2_BYTES;
        const uint32_t aOff = (uint32_t)(wm * 64 + g) * 128 + c * 8;
        const uint32_t bOff = (uint32_t)(wn * 64 + g) * 128 + c * 8;

        // 8 k-slices (2 sub-tiles x 4), fragment double-buffered
        float2 af[2][4][2], bf[2][8];

        #define LOADF(buf, ss) do {                                             \
            const int sub_ = (ss) >> 2, s_ = (ss) & 3;                          \
            const char* Ab_ = stg + sub_ * SUB_BYTES;                           \
            const char* Bb_ = Ab_ + SA_BYTES;                                   \
            const int sw_ = ((s_ + g) & 3) * 32;                                \
            _Pragma("unroll")                                                   \
            for (int mi = 0; mi < 4; ++mi) {                                    \
                af[buf][mi][0] = *(const float2*)(Ab_ + aOff + mi * (16 * 128) + sw_); \
                af[buf][mi][1] = *(const float2*)(Ab_ + aOff + mi * (16 * 128) + 8 * 128 + sw_); \
            }                                                                   \
            _Pragma("unroll")                                                   \
            for (int nj = 0; nj < 8; ++nj)                                      \
                bf[buf][nj] = *(const float2*)(Bb_ + bOff + nj * (8 * 128) + sw_); \
        } while (0)

        LOADF(0, 0);
        #pragma unroll
        for (int ss = 0; ss < 8; ++ss) {
            if (ss < 7) LOADF((ss + 1) & 1, ss + 1);
            const int b = ss & 1;
            #pragma unroll
            for (int mi = 0; mi < 4; ++mi)
                #pragma unroll
                for (int nj = 0; nj < 8; ++nj)
                    mma16818(acc[mi][nj], af[b][mi][0], af[b][mi][1], bf[b][nj]);
        }
        #undef LOADF
    }

    #pragma unroll
    for (int mi = 0; mi < 4; ++mi) {
        const int r = row0 + wm * 64 + mi * 16 + g;
        #pragma unroll
        for (int nj = 0; nj < 8; ++nj) {
            const int cg = col0 + wn * 64 + nj * 8 + c * 2;
            const float2 bv = *(const float2*)&bias[cg];
            float2 o0, o1;
            o0.x = acc[mi][nj][0] + bv.x;  o0.y = acc[mi][nj][1] + bv.y;
            o1.x = acc[mi][nj][2] + bv.x;  o1.y = acc[mi][nj][3] + bv.y;
            *(float2*)&out[(size_t)r * DOUT + cg]       = o0;
            *(float2*)&out[(size_t)(r + 8) * DOUT + cg] = o1;
        }
    }
}

// ---------------------------------------------------------------------------
extern "C" void kernel_launch(void* const* d_in, const int* in_sizes, int n_in,
                              void* d_out, int out_size)
{
    const float* x    = (const float*)d_in[0];   // [8192, 4096]
    const float* A    = (const float*)d_in[1];   // [64, 4096]
    const float* Bm   = (const float*)d_in[2];   // [4096, 64]
    const float* W    = (const float*)d_in[3];   // [4096, 4096]
    const float* bias = (const float*)d_in[4];   // [4096]
    float* out = (float*)d_out;                  // [8192, 4096]

    float* xp; cudaGetSymbolAddress((void**)&xp, g_x32);
    float* wp; cudaGetSymbolAddress((void**)&wp, g_w32);
    float* bp; cudaGetSymbolAddress((void**)&bp, g_b32);
    float* ap; cudaGetSymbolAddress((void**)&ap, g_a32);

    {
        int n4x = MROWS * DIN / 4;
        int n4w = DOUT * DIN / 4;
        int n4b = DOUT * RNK / 4;
        int n4a = RNK * DIN / 4;
        prep_kernel<<<(n4x + 255) / 256, 256>>>(x,  xp, n4x);
        prep_kernel<<<(n4w + 255) / 256, 256>>>(W,  wp, n4w);
        prep_kernel<<<(n4b + 255) / 256, 256>>>(Bm, bp, n4b);
        prep_kernel<<<(n4a + 255) / 256, 256>>>(A,  ap, n4a);
    }

    cudaFuncSetAttribute(lora_z_mma_kernel,
                         cudaFuncAttributeMaxDynamicSharedMemorySize, Z_SMEM);
    {
        dim3 gz(MROWS / 128, KSPL);   // (64, 8)
        lora_z_mma_kernel<<<gz, 256, Z_SMEM>>>();
        lora_topk_kernel<<<MROWS / 64, 256>>>();
    }

    cudaFuncSetAttribute(tf32_gemm_kernel,
                         cudaFuncAttributeMaxDynamicSharedMemorySize, SMEMB);
    dim3 grid(DOUT / BN, MROWS / BM);   // (16, 64) = 1024 CTAs
    tf32_gemm_kernel<<<grid, 256, SMEMB>>>(bias, out);
}

// round 9
// speedup vs baseline: 6.9872x; 1.8622x over previous
#include <cuda_runtime.h>
#include <cuda_fp16.h>
#include <cstdint>

// FixedTopKLoRALinear — Round 8: fp16 mma.sync.m16n8k16 (2x tf32 rate,
// identical 11-bit significand precision), all operand bytes halved.
//   out = x @ W^T + bias + soft_topk(x @ A^T) @ B^T    (SCALE = 1.0)
// x[8192,4096] W[4096,4096] A[64,4096] B[4096,64] bias[4096], all fp32.

typedef unsigned long long u64;

#define DIN   4096
#define DOUT  4096
#define MROWS 8192
#define RNK   64
#define RNK2  128                          // zero-padded rank stride
#define KTOP  16
#define KSPL  8
#define KSEG  (DIN / KSPL)                 // 512

// ---- main GEMM tiling (fp16) ----
#define BM 128
#define BN 256
#define BKS 64                             // k per sub-tile (128B row)
#define BK  128                            // k per iteration (2 sub-tiles)
#define KCH (DIN / BK)                     // 32
#define NIT (KCH + 1)                      // 33 (last = LoRA, k=128 padded)
#define SA_BYTES (BM * 128)                // 16384 per sub-tile
#define SB_BYTES (BN * 128)                // 32768
#define SUB_BYTES (SA_BYTES + SB_BYTES)    // 49152
#define STG_BYTES (2 * SUB_BYTES)          // 98304 per stage
#define SMEMB (2 * STG_BYTES)              // 196608

// ---- kernel-1 tiling (CTA 128x64, K-seg 512, k64/iter, 8 iters) ----
#define ZSTAGES 4
#define Z_SA (128 * 128)                   // 16384
#define Z_SB (64 * 128)                    // 8192
#define Z_STG (Z_SA + Z_SB)                // 24576
#define Z_SMEM (ZSTAGES * Z_STG)           // 98304
#define Z_ITERS (KSEG / BKS)               // 8

// fp16 operands
__device__ __half g_xh[(size_t)MROWS * DIN];   // 64 MB
__device__ __half g_wh[(size_t)DOUT * DIN];    // 32 MB
__device__ __half g_ah[(size_t)RNK * DIN];     // 0.5 MB
__device__ __half g_bh[(size_t)DOUT * RNK2];   // 1 MB (cols 64..127 zero)
__device__ __half g_zh[(size_t)MROWS * RNK2];  // 2 MB (cols 64..127 zero)
__device__ float  g_zp[(size_t)KSPL * MROWS * RNK];  // 16 MB split-K partials

// ---------------------------------------------------------------------------
// helpers
// ---------------------------------------------------------------------------
__device__ __forceinline__ uint32_t smem_u32(const void* p) {
    uint32_t a;
    asm("{ .reg .u64 t; cvta.to.shared.u64 t, %1; cvt.u32.u64 %0, t; }"
        : "=r"(a) : "l"(p));
    return a;
}
__device__ __forceinline__ void cpa16(uint32_t dst, const void* src) {
    asm volatile("cp.async.cg.shared.global [%0], [%1], 16;" :: "r"(dst), "l"(src));
}
__device__ __forceinline__ void cp_commit() {
    asm volatile("cp.async.commit_group;" ::: "memory");
}
__device__ __forceinline__ void cp_wait0() {
    asm volatile("cp.async.wait_group 0;" ::: "memory");
}
__device__ __forceinline__ void cp_wait2() {
    asm volatile("cp.async.wait_group 2;" ::: "memory");
}
__device__ __forceinline__ uint32_t f2h2(float lo, float hi) {
    __half2 h = __floats2half2_rn(lo, hi);
    return *reinterpret_cast<uint32_t*>(&h);
}
// m16n8k16 f16 mma, fp32 acc. a02 = (a0,a2) row g, a13 = (a1,a3) row g+8,
// b = (b0,b1). k mapping: lane c covers the contiguous half-quad 4c..4c+3,
// identically on A and B sides (permutation-consistent).
__device__ __forceinline__ void mmaf16(float* d, uint2 a02, uint2 a13, uint2 b) {
    asm("mma.sync.aligned.m16n8k16.row.col.f32.f16.f16.f32 "
        "{%0,%1,%2,%3}, {%4,%5,%6,%7}, {%8,%9}, {%0,%1,%2,%3};"
        : "+f"(d[0]), "+f"(d[1]), "+f"(d[2]), "+f"(d[3])
        : "r"(a02.x), "r"(a13.x), "r"(a02.y), "r"(a13.y),
          "r"(b.x), "r"(b.y));
}

// ---------------------------------------------------------------------------
// Prep: fp32 -> fp16 (RN), 8 elems / thread
// ---------------------------------------------------------------------------
__global__ __launch_bounds__(256) void prep_h_kernel(
    const float* __restrict__ in, __half* __restrict__ out, int n8)
{
    int i = blockIdx.x * blockDim.x + threadIdx.x;
    if (i >= n8) return;
    float4 a = ((const float4*)in)[2 * i];
    float4 b = ((const float4*)in)[2 * i + 1];
    uint4 o;
    o.x = f2h2(a.x, a.y); o.y = f2h2(a.z, a.w);
    o.z = f2h2(b.x, b.y); o.w = f2h2(b.z, b.w);
    *(uint4*)&out[(size_t)i * 8] = o;
}

// B prep: [DOUT][RNK] fp32 -> [DOUT][RNK2] fp16 with cols 64..127 zeroed.
__global__ __launch_bounds__(256) void prep_b_kernel(const float* __restrict__ in)
{
    int i = blockIdx.x * blockDim.x + threadIdx.x;   // DOUT * 8 threads
    if (i >= DOUT * 8) return;
    const int row = i >> 3, chunk = i & 7;
    const float4 a = ((const float4*)in)[(size_t)row * (RNK / 4) + 2 * chunk];
    const float4 b = ((const float4*)in)[(size_t)row * (RNK / 4) + 2 * chunk + 1];
    uint4 o;
    o.x = f2h2(a.x, a.y); o.y = f2h2(a.z, a.w);
    o.z = f2h2(b.x, b.y); o.w = f2h2(b.z, b.w);
    *(uint4*)&g_bh[(size_t)row * RNK2 + chunk * 8] = o;
    *(uint4*)&g_bh[(size_t)row * RNK2 + 64 + chunk * 8] = make_uint4(0, 0, 0, 0);
}

// ---------------------------------------------------------------------------
// Kernel 1a: split-K partial z = x[:, seg] @ A[:, seg]^T via fp16 mma.
// grid (64, 8). CTA 128x64, warp tile 32x32 (4x2 warps). 8 iters of k64.
// ---------------------------------------------------------------------------
__global__ __launch_bounds__(256, 2) void lora_z_mma_kernel()
{
    extern __shared__ __align__(16) char sm[];
    const uint32_t sA = smem_u32(sm);

    const int tid  = threadIdx.x;
    const int lane = tid & 31;
    const int wid  = tid >> 5;
    const int wm   = wid >> 1;
    const int wn   = wid & 1;
    const int row0 = blockIdx.x * 128;
    const int kbase = blockIdx.y * KSEG;

    const int lr = tid >> 3;              // 0..31
    const int lc = tid & 7;               // 16B chunk of 128B row
    const uint32_t swd = ((((lc >> 1) + (lr & 3)) & 3) * 32) + (lc & 1) * 16;
    const uint32_t dA = (uint32_t)lr * 128 + swd;

    const __half* pX = g_xh + (size_t)(row0 + lr) * DIN + kbase + lc * 8;
    const __half* pA = g_ah + (size_t)lr * DIN + kbase + lc * 8;

    #define Z_ISSUE(nit) do {                                                  \
        if ((nit) < Z_ITERS) {                                                 \
            const uint32_t sb = sA + ((nit) & (ZSTAGES - 1)) * Z_STG;           \
            const __half* a0 = pX + (size_t)(nit) * BKS;                       \
            const __half* b0 = pA + (size_t)(nit) * BKS;                       \
            _Pragma("unroll")                                                  \
            for (int j = 0; j < 4; ++j)                                        \
                cpa16(sb + dA + j * (32 * 128), a0 + (size_t)j * 32 * DIN);    \
            _Pragma("unroll")                                                  \
            for (int j = 0; j < 2; ++j)                                        \
                cpa16(sb + Z_SA + dA + j * (32 * 128), b0 + (size_t)j * 32 * DIN); \
        }                                                                      \
        cp_commit();                                                           \
    } while (0)

    float acc[2][4][4];
    #pragma unroll
    for (int i = 0; i < 2; ++i)
        #pragma unroll
        for (int j = 0; j < 4; ++j)
            #pragma unroll
            for (int q = 0; q < 4; ++q) acc[i][j][q] = 0.0f;

    const int g = lane >> 2;
    const int c = lane & 3;
    const char* smc = sm;

    Z_ISSUE(0);
    Z_ISSUE(1);
    Z_ISSUE(2);

    for (int it = 0; it < Z_ITERS; ++it) {
        cp_wait2();
        __syncthreads();
        Z_ISSUE(it + 3);

        const char* Ab = smc + (it & (ZSTAGES - 1)) * Z_STG;
        const char* Bb = Ab + Z_SA;
        const char* aBase = Ab + (size_t)(wm * 32 + g) * 128 + c * 8;
        const char* bBase = Bb + (size_t)(wn * 32 + g) * 128 + c * 8;

        #pragma unroll
        for (int s = 0; s < 4; ++s) {       // 4 k16 slices per k64 iter
            const int sw = ((s + g) & 3) * 32;
            uint2 af[2][2], bf[4];
            #pragma unroll
            for (int mi = 0; mi < 2; ++mi) {
                af[mi][0] = *(const uint2*)(aBase + mi * (16 * 128) + sw);
                af[mi][1] = *(const uint2*)(aBase + mi * (16 * 128) + 8 * 128 + sw);
            }
            #pragma unroll
            for (int nj = 0; nj < 4; ++nj)
                bf[nj] = *(const uint2*)(bBase + nj * (8 * 128) + sw);
            #pragma unroll
            for (int mi = 0; mi < 2; ++mi)
                #pragma unroll
                for (int nj = 0; nj < 4; ++nj)
                    mmaf16(acc[mi][nj], af[mi][0], af[mi][1], bf[nj]);
        }
    }

    float* zp = g_zp + (size_t)blockIdx.y * MROWS * RNK;
    #pragma unroll
    for (int mi = 0; mi < 2; ++mi) {
        const int r = row0 + wm * 32 + mi * 16 + g;
        #pragma unroll
        for (int nj = 0; nj < 4; ++nj) {
            const int cg = wn * 32 + nj * 8 + c * 2;
            float2 o0, o1;
            o0.x = acc[mi][nj][0]; o0.y = acc[mi][nj][1];
            o1.x = acc[mi][nj][2]; o1.y = acc[mi][nj][3];
            *(float2*)&zp[(size_t)r * RNK + cg]       = o0;
            *(float2*)&zp[(size_t)(r + 8) * RNK + cg] = o1;
        }
    }
}

// ---------------------------------------------------------------------------
// Kernel 1b: reduce 8 partials + exact soft top-k, write fp16 g_zh (padded).
// ---------------------------------------------------------------------------
__global__ __launch_bounds__(256) void lora_topk_kernel()
{
    const int tid  = threadIdx.x;
    const int wid  = tid >> 5;
    const int lane = tid & 31;
    const int row0 = blockIdx.x * 64;

    for (int rr = 0; rr < 8; ++rr) {
        const int row = row0 + wid * 8 + rr;
        const size_t base = (size_t)row * RNK;
        float v0 = 0.0f, v1 = 0.0f;
        #pragma unroll
        for (int s = 0; s < KSPL; ++s) {
            const float* zp = g_zp + (size_t)s * MROWS * RNK + base;
            v0 += zp[lane];
            v1 += zp[lane + 32];
        }
        const float a0 = fabsf(v0), a1 = fabsf(v1);
        float x0 = a0, x1 = a1;
        float thr = 0.0f;
        #pragma unroll
        for (int t = 0; t < KTOP; ++t) {
            float m = fmaxf(x0, x1);
            #pragma unroll
            for (int o = 16; o > 0; o >>= 1)
                m = fmaxf(m, __shfl_xor_sync(0xffffffffu, m, o));
            thr = m;
            unsigned ball = __ballot_sync(0xffffffffu, (x0 == m) || (x1 == m));
            int leader = __ffs(ball) - 1;
            if (lane == leader) {
                if (x0 == m) x0 = -1.0f; else x1 = -1.0f;
            }
        }
        const float m0 = 1.0f / (1.0f + expf((thr - a0) * 10.0f));
        const float m1 = 1.0f / (1.0f + expf((thr - a1) * 10.0f));
        __half* zo = g_zh + (size_t)row * RNK2;
        zo[lane]      = __float2half_rn(v0 * m0);
        zo[lane + 32] = __float2half_rn(v1 * m1);
        zo[lane + 64] = __float2half_rn(0.0f);
        zo[lane + 96] = __float2half_rn(0.0f);
    }
}

// ---------------------------------------------------------------------------
// Kernel 2: fp16 mma.sync GEMM. CTA 128x256, warp 64x64, BK=128 (2 sub-tiles
// of k64), 2-stage cp.async pipeline, fragment double buffering, 1 sync/iter.
// Iter 32 = LoRA (g_zh / g_bh, rank padded to 128).
// ---------------------------------------------------------------------------
__global__ __launch_bounds__(256, 1) void h_gemm_kernel(
    const float* __restrict__ bias, float* __restrict__ out)
{
    extern __shared__ __align__(16) char sm[];
    const uint32_t sA = smem_u32(sm);

    const int tid  = threadIdx.x;
    const int lane = tid & 31;
    const int wid  = tid >> 5;
    const int wm   = wid >> 2;            // 0..1
    const int wn   = wid & 3;             // 0..3
    const int row0 = blockIdx.y * BM;
    const int col0 = blockIdx.x * BN;

    const int lr = tid >> 3;              // 0..31
    const int lc = tid & 7;
    const uint32_t swd = ((((lc >> 1) + (lr & 3)) & 3) * 32) + (lc & 1) * 16;
    const uint32_t dA = (uint32_t)lr * 128 + swd;

    const __half* pAx = g_xh + (size_t)(row0 + lr) * DIN + lc * 8;
    const __half* pBw = g_wh + (size_t)(col0 + lr) * DIN + lc * 8;
    const __half* pAz = g_zh + (size_t)(row0 + lr) * RNK2 + lc * 8;
    const __half* pBb = g_bh + (size_t)(col0 + lr) * RNK2 + lc * 8;

    // one ISSUE = BK=128 iter = 2 sub-tiles of k64, 24 cp.async/thread
    #define ISSUE(nit) do {                                                     \
        if ((nit) < NIT) {                                                      \
            const uint32_t sb = sA + ((nit) & 1) * STG_BYTES;                   \
            if ((nit) < KCH) {                                                  \
                _Pragma("unroll")                                               \
                for (int sub = 0; sub < 2; ++sub) {                             \
                    const uint32_t st = sb + sub * SUB_BYTES;                   \
                    const __half* a0 = pAx + (size_t)(nit) * BK + sub * BKS;    \
                    const __half* b0 = pBw + (size_t)(nit) * BK + sub * BKS;    \
                    _Pragma("unroll")                                           \
                    for (int j = 0; j < 4; ++j)                                 \
                        cpa16(st + dA + j * (32 * 128), a0 + (size_t)j * 32 * DIN); \
                    _Pragma("unroll")                                           \
                    for (int j = 0; j < 8; ++j)                                 \
                        cpa16(st + SA_BYTES + dA + j * (32 * 128), b0 + (size_t)j * 32 * DIN); \
                }                                                               \
            } else {                                                            \
                _Pragma("unroll")                                               \
                for (int sub = 0; sub < 2; ++sub) {                             \
                    const uint32_t st = sb + sub * SUB_BYTES;                   \
                    const __half* a0 = pAz + sub * BKS;                         \
                    const __half* b0 = pBb + sub * BKS;                         \
                    _Pragma("unroll")                                           \
                    for (int j = 0; j < 4; ++j)                                 \
                        cpa16(st + dA + j * (32 * 128), a0 + (size_t)j * 32 * RNK2); \
                    _Pragma("unroll")                                           \
                    for (int j = 0; j < 8; ++j)                                 \
                        cpa16(st + SA_BYTES + dA + j * (32 * 128), b0 + (size_t)j * 32 * RNK2); \
                }                                                               \
            }                                                                   \
        }                                                                       \
        cp_commit();                                                            \
    } while (0)

    float acc[4][8][4];
    #pragma unroll
    for (int i = 0; i < 4; ++i)
        #pragma unroll
        for (int j = 0; j < 8; ++j)
            #pragma unroll
            for (int q = 0; q < 4; ++q) acc[i][j][q] = 0.0f;

    const int g = lane >> 2;
    const int c = lane & 3;
    const char* smc = sm;

    ISSUE(0);

    for (int it = 0; it < NIT; ++it) {
        cp_wait0();
        __syncthreads();
        ISSUE(it + 1);

        const char* stg = smc + (it & 1) * STG_BYTES;
        const uint32_t aOff = (uint32_t)(wm * 64 + g) * 128 + c * 8;
        const uint32_t bOff = (uint32_t)(wn * 64 + g) * 128 + c * 8;

        // 8 k16-slices (2 sub-tiles x 4), fragment double-buffered
        uint2 af[2][4][2], bf[2][8];

        #define LOADF(buf, ss) do {                                             \
            const int sub_ = (ss) >> 2, s_ = (ss) & 3;                          \
            const char* Ab_ = stg + sub_ * SUB_BYTES;                           \
            const char* Bb_ = Ab_ + SA_BYTES;                                   \
            const int sw_ = ((s_ + g) & 3) * 32;                                \
            _Pragma("unroll")                                                   \
            for (int mi = 0; mi < 4; ++mi) {                                    \
                af[buf][mi][0] = *(const uint2*)(Ab_ + aOff + mi * (16 * 128) + sw_); \
                af[buf][mi][1] = *(const uint2*)(Ab_ + aOff + mi * (16 * 128) + 8 * 128 + sw_); \
            }                                                                   \
            _Pragma("unroll")                                                   \
            for (int nj = 0; nj < 8; ++nj)                                      \
                bf[buf][nj] = *(const uint2*)(Bb_ + bOff + nj * (8 * 128) + sw_); \
        } while (0)

        LOADF(0, 0);
        #pragma unroll
        for (int ss = 0; ss < 8; ++ss) {
            if (ss < 7) LOADF((ss + 1) & 1, ss + 1);
            const int b = ss & 1;
            #pragma unroll
            for (int mi = 0; mi < 4; ++mi)
                #pragma unroll
                for (int nj = 0; nj < 8; ++nj)
                    mmaf16(acc[mi][nj], af[b][mi][0], af[b][mi][1], bf[b][nj]);
        }
        #undef LOADF
    }

    #pragma unroll
    for (int mi = 0; mi < 4; ++mi) {
        const int r = row0 + wm * 64 + mi * 16 + g;
        #pragma unroll
        for (int nj = 0; nj < 8; ++nj) {
            const int cg = col0 + wn * 64 + nj * 8 + c * 2;
            const float2 bv = *(const float2*)&bias[cg];
            float2 o0, o1;
            o0.x = acc[mi][nj][0] + bv.x;  o0.y = acc[mi][nj][1] + bv.y;
            o1.x = acc[mi][nj][2] + bv.x;  o1.y = acc[mi][nj][3] + bv.y;
            *(float2*)&out[(size_t)r * DOUT + cg]       = o0;
            *(float2*)&out[(size_t)(r + 8) * DOUT + cg] = o1;
        }
    }
}

// ---------------------------------------------------------------------------
extern "C" void kernel_launch(void* const* d_in, const int* in_sizes, int n_in,
                              void* d_out, int out_size)
{
    const float* x    = (const float*)d_in[0];   // [8192, 4096]
    const float* A    = (const float*)d_in[1];   // [64, 4096]
    const float* Bm   = (const float*)d_in[2];   // [4096, 64]
    const float* W    = (const float*)d_in[3];   // [4096, 4096]
    const float* bias = (const float*)d_in[4];   // [4096]
    float* out = (float*)d_out;                  // [8192, 4096]

    __half* xp; cudaGetSymbolAddress((void**)&xp, g_xh);
    __half* wp; cudaGetSymbolAddress((void**)&wp, g_wh);
    __half* ap; cudaGetSymbolAddress((void**)&ap, g_ah);

    {
        int n8x = MROWS * DIN / 8;
        int n8w = DOUT * DIN / 8;
        int n8a = RNK * DIN / 8;
        prep_h_kernel<<<(n8x + 255) / 256, 256>>>(x, xp, n8x);
        prep_h_kernel<<<(n8w + 255) / 256, 256>>>(W, wp, n8w);
        prep_h_kernel<<<(n8a + 255) / 256, 256>>>(A, ap, n8a);
        prep_b_kernel<<<(DOUT * 8 + 255) / 256, 256>>>(Bm);
    }

    cudaFuncSetAttribute(lora_z_mma_kernel,
                         cudaFuncAttributeMaxDynamicSharedMemorySize, Z_SMEM);
    {
        dim3 gz(MROWS / 128, KSPL);   // (64, 8)
        lora_z_mma_kernel<<<gz, 256, Z_SMEM>>>();
        lora_topk_kernel<<<MROWS / 64, 256>>>();
    }

    cudaFuncSetAttribute(h_gemm_kernel,
                         cudaFuncAttributeMaxDynamicSharedMemorySize, SMEMB);
    dim3 grid(DOUT / BN, MROWS / BM);   // (16, 64) = 1024 CTAs
    h_gemm_kernel<<<grid, 256, SMEMB>>>(bias, out);
}